// round 2
// baseline (speedup 1.0000x reference)
#include <cuda_runtime.h>
#include <cstdint>
#include <math.h>

#define DIM   512
#define BATCH 32
#define TLEN  2048
#define MROWS (BATCH * TLEN)

typedef unsigned long long u64;
typedef unsigned int u32;

// ---------------- scratch (device globals; no allocation allowed) ----------
__device__ float g_S0[(size_t)MROWS * DIM];  // xn
__device__ float g_S1[(size_t)MROWS * DIM];  // nh / gnh
__device__ float g_S2[(size_t)MROWS * DIM];  // ifg / gate logits
__device__ float g_S3[(size_t)MROWS * DIM];  // h (layer outputs)

// ---------------- f32x2 helpers -------------------------------------------
__device__ __forceinline__ u64 pk2(float x, float y) {
    u64 r; asm("mov.b64 %0, {%1,%2};" : "=l"(r) : "f"(x), "f"(y)); return r;
}
__device__ __forceinline__ float2 up2(u64 v) {
    float2 r; asm("mov.b64 {%0,%1}, %2;" : "=f"(r.x), "=f"(r.y) : "l"(v)); return r;
}
#define FMA2(d, a, b) asm("fma.rn.f32x2 %0, %1, %2, %0;" : "+l"(d) : "l"(a), "l"(b))

__device__ __forceinline__ u32 s2u(const void* p) {
    u32 a;
    asm("{ .reg .u64 t; cvta.to.shared.u64 t, %1; cvt.u32.u64 %0, t; }" : "=r"(a) : "l"(p));
    return a;
}
#define CLUSTER_SYNC() do { \
    asm volatile("barrier.cluster.arrive.aligned;" ::: "memory"); \
    asm volatile("barrier.cluster.wait.aligned;" ::: "memory"); \
} while (0)

// ---------------- rmsnorm ---------------------------------------------------
// one CTA (128 threads) per token; each thread owns one float4 (512/4 = 128)
__global__ __launch_bounds__(128) void rmsnorm_kernel(
    const float* __restrict__ x, const float* __restrict__ gamma,
    float* __restrict__ xn)
{
    const size_t row = blockIdx.x;
    const int tid = threadIdx.x;
    float4 v = ((const float4*)(x + row * DIM))[tid];
    float ss = v.x * v.x + v.y * v.y + v.z * v.z + v.w * v.w;
    #pragma unroll
    for (int o = 16; o; o >>= 1) ss += __shfl_xor_sync(0xffffffffu, ss, o);
    __shared__ float sred[4];
    if ((tid & 31) == 0) sred[tid >> 5] = ss;
    __syncthreads();
    float tot = sred[0] + sred[1] + sred[2] + sred[3];
    float n = fmaxf(sqrtf(tot), 1e-12f);
    float s = 22.62741699796952f / n;  // sqrt(512)
    float4 gv = ((const float4*)gamma)[tid];
    float4 o;
    o.x = v.x * s * (gv.x + 1.f);
    o.y = v.y * s * (gv.y + 1.f);
    o.z = v.z * s * (gv.z + 1.f);
    o.w = v.w * s * (gv.w + 1.f);
    ((float4*)(xn + row * DIM))[tid] = o;
}

// ---------------- SGEMM (f32x2), C[M,512] = act(A[M,512] @ W[512,512]) ------
// 128x128 tile, BK=16, 256 threads, 8x8 per thread.
// act: 0 = none, 1 = tanh.  accum: C += result instead of C = result.
__global__ __launch_bounds__(256, 2) void gemm512(
    const float* __restrict__ A, const float* __restrict__ W,
    float* __restrict__ C, int act, int accum)
{
    __shared__ __align__(16) float As[16][132];
    __shared__ __align__(16) float Bs[16][132];
    const int tid = threadIdx.x;
    const int tx = tid & 15, ty = tid >> 4;
    const size_t m0 = (size_t)blockIdx.y * 128;
    const int n0 = blockIdx.x * 128;

    u64 acc[8][4];
    #pragma unroll
    for (int i = 0; i < 8; i++)
        #pragma unroll
        for (int jj = 0; jj < 4; jj++) acc[i][jj] = 0ull;  // bits of (0.f,0.f)

    const int ar = tid >> 2, ac4 = (tid & 3) * 4;
    const int br = tid >> 4, bc4 = (tid & 15) * 4;

    for (int kt = 0; kt < 512; kt += 16) {
        float4 a0 = *(const float4*)(A + (m0 + ar) * 512 + kt + ac4);
        float4 a1 = *(const float4*)(A + (m0 + ar + 64) * 512 + kt + ac4);
        float4 b0 = *(const float4*)(W + (size_t)(kt + br) * 512 + n0 + bc4);
        float4 b1 = *(const float4*)(W + (size_t)(kt + br) * 512 + n0 + bc4 + 64);
        __syncthreads();
        As[ac4 + 0][ar] = a0.x; As[ac4 + 1][ar] = a0.y;
        As[ac4 + 2][ar] = a0.z; As[ac4 + 3][ar] = a0.w;
        As[ac4 + 0][ar + 64] = a1.x; As[ac4 + 1][ar + 64] = a1.y;
        As[ac4 + 2][ar + 64] = a1.z; As[ac4 + 3][ar + 64] = a1.w;
        *(float4*)&Bs[br][bc4] = b0;
        *(float4*)&Bs[br][bc4 + 64] = b1;
        __syncthreads();
        #pragma unroll
        for (int k = 0; k < 16; k++) {
            float4 fa0 = *(const float4*)&As[k][ty * 4];
            float4 fa1 = *(const float4*)&As[k][ty * 4 + 64];
            float4 fb0 = *(const float4*)&Bs[k][tx * 4];
            float4 fb1 = *(const float4*)&Bs[k][tx * 4 + 64];
            u64 bp0 = pk2(fb0.x, fb0.y), bp1 = pk2(fb0.z, fb0.w);
            u64 bp2 = pk2(fb1.x, fb1.y), bp3 = pk2(fb1.z, fb1.w);
            float av[8] = {fa0.x, fa0.y, fa0.z, fa0.w, fa1.x, fa1.y, fa1.z, fa1.w};
            #pragma unroll
            for (int i = 0; i < 8; i++) {
                u64 ad = pk2(av[i], av[i]);
                FMA2(acc[i][0], ad, bp0);
                FMA2(acc[i][1], ad, bp1);
                FMA2(acc[i][2], ad, bp2);
                FMA2(acc[i][3], ad, bp3);
            }
        }
    }
    #pragma unroll
    for (int i = 0; i < 8; i++) {
        int row = (i < 4) ? (ty * 4 + i) : (64 + ty * 4 + (i - 4));
        float* cp = C + (m0 + row) * 512 + n0;
        #pragma unroll
        for (int jh = 0; jh < 2; jh++) {
            float2 v0 = up2(acc[i][jh * 2]);
            float2 v1 = up2(acc[i][jh * 2 + 1]);
            float4 v = make_float4(v0.x, v0.y, v1.x, v1.y);
            if (act) {
                v.x = tanhf(v.x); v.y = tanhf(v.y);
                v.z = tanhf(v.z); v.w = tanhf(v.w);
            }
            int col = jh * 64 + tx * 4;
            if (accum) {
                float4 o = *(float4*)(cp + col);
                v.x += o.x; v.y += o.y; v.z += o.z; v.w += o.w;
            }
            *(float4*)(cp + col) = v;
        }
    }
}

// ---------------- LRU recurrence -------------------------------------------
// One cluster of 8 CTAs handles 2 batches. Each CTA: 512 threads, owns 64
// output columns, Whf columns in registers (64 packed f32x2 regs / thread).
// Thread (jl = tid>>3, s = tid&7): output j = crank*64 + jl, k-slice s
// (k in [64s, 64s+64)). Dot reduced over s via shfl.bfly. New h broadcast to
// all 8 CTAs via DSMEM (thread with slice s writes rank s), double-buffered,
// one cluster.sync per step.
__global__ void __cluster_dims__(8, 1, 1) __launch_bounds__(512, 1)
lru_scan(const float* __restrict__ nh, const float* __restrict__ ifg,
         const float* __restrict__ Whf, const float* __restrict__ bhf,
         float* __restrict__ hout)
{
    __shared__ __align__(16) float hbuf[2][2][DIM];  // [buffer][batch][j]
    const u32 tid = threadIdx.x;
    const u32 jl = tid >> 3, s = tid & 7;
    u32 crank; asm("mov.u32 %0, %%cluster_ctarank;" : "=r"(crank));
    const u32 j = crank * 64 + jl;
    const u32 cl = blockIdx.x >> 3;

    // weights, packed + reordered so the smem reads below are conflict-free
    u64 wp[32];
    #pragma unroll
    for (int ii = 0; ii < 16; ii++) {
        u32 i4 = (ii + s) & 15;
        u32 k = s * 64 + i4 * 4;
        float w0 = Whf[(size_t)(k + 0) * DIM + j];
        float w1 = Whf[(size_t)(k + 1) * DIM + j];
        float w2 = Whf[(size_t)(k + 2) * DIM + j];
        float w3 = Whf[(size_t)(k + 3) * DIM + j];
        wp[2 * ii] = pk2(w0, w1);
        wp[2 * ii + 1] = pk2(w2, w3);
    }
    const float bias = bhf[j];

    hbuf[0][0][tid] = 0.f;
    hbuf[0][1][tid] = 0.f;

    u32 a00 = s2u(&hbuf[0][0][j]), a01 = s2u(&hbuf[0][1][j]);
    u32 a10 = s2u(&hbuf[1][0][j]), a11 = s2u(&hbuf[1][1][j]);
    u32 r00, r01, r10, r11;
    asm("mapa.shared::cluster.u32 %0, %1, %2;" : "=r"(r00) : "r"(a00), "r"(s));
    asm("mapa.shared::cluster.u32 %0, %1, %2;" : "=r"(r01) : "r"(a01), "r"(s));
    asm("mapa.shared::cluster.u32 %0, %1, %2;" : "=r"(r10) : "r"(a10), "r"(s));
    asm("mapa.shared::cluster.u32 %0, %1, %2;" : "=r"(r11) : "r"(a11), "r"(s));

    const size_t base0 = ((size_t)(cl * 2 + 0) * TLEN) * DIM + j;
    const size_t base1 = ((size_t)(cl * 2 + 1) * TLEN) * DIM + j;

    CLUSTER_SYNC();

    float nv0 = nh[base0], iv0 = ifg[base0];
    float nv1 = nh[base1], iv1 = ifg[base1];
    float h0 = 0.f, h1 = 0.f;
    int p = 0;
    for (int t = 0; t < TLEN; t++) {
        const ulonglong2* hq0 = (const ulonglong2*)hbuf[p][0];
        const ulonglong2* hq1 = (const ulonglong2*)hbuf[p][1];
        u64 acc0a = 0ull, acc0b = 0ull, acc1a = 0ull, acc1b = 0ull;
        #pragma unroll
        for (int ii = 0; ii < 16; ii++) {
            u32 idx = s * 16 + ((ii + s) & 15);
            ulonglong2 hv0 = hq0[idx];
            ulonglong2 hv1 = hq1[idx];
            FMA2(acc0a, wp[2 * ii], hv0.x);
            FMA2(acc0b, wp[2 * ii + 1], hv0.y);
            FMA2(acc1a, wp[2 * ii], hv1.x);
            FMA2(acc1b, wp[2 * ii + 1], hv1.y);
        }
        float2 u0 = up2(acc0a), u0b = up2(acc0b);
        float2 u1 = up2(acc1a), u1b = up2(acc1b);
        float d0 = (u0.x + u0.y) + (u0b.x + u0b.y);
        float d1 = (u1.x + u1.y) + (u1b.x + u1b.y);
        d0 += __shfl_xor_sync(0xffffffffu, d0, 1);
        d0 += __shfl_xor_sync(0xffffffffu, d0, 2);
        d0 += __shfl_xor_sync(0xffffffffu, d0, 4);
        d1 += __shfl_xor_sync(0xffffffffu, d1, 1);
        d1 += __shfl_xor_sync(0xffffffffu, d1, 2);
        d1 += __shfl_xor_sync(0xffffffffu, d1, 4);
        float g0 = 1.f / (1.f + expf(-(d0 + bias + iv0)));
        float g1 = 1.f / (1.f + expf(-(d1 + bias + iv1)));
        float hn0 = fmaf(g0, nv0 - h0, h0);
        float hn1 = fmaf(g1, nv1 - h1, h1);
        h0 = hn0; h1 = hn1;
        if (t + 1 < TLEN) {
            nv0 = nh[base0 + (size_t)(t + 1) * DIM];
            iv0 = ifg[base0 + (size_t)(t + 1) * DIM];
            nv1 = nh[base1 + (size_t)(t + 1) * DIM];
            iv1 = ifg[base1 + (size_t)(t + 1) * DIM];
        }
        u32 d0a = p ? r00 : r10;  // write buffer p^1
        u32 d1a = p ? r01 : r11;
        asm volatile("st.shared::cluster.f32 [%0], %1;" :: "r"(d0a), "f"(hn0) : "memory");
        asm volatile("st.shared::cluster.f32 [%0], %1;" :: "r"(d1a), "f"(hn1) : "memory");
        if (s == 0) {
            hout[base0 + (size_t)t * DIM] = hn0;
            hout[base1 + (size_t)t * DIM] = hn1;
        }
        CLUSTER_SYNC();
        p ^= 1;
    }
}

// ---------------- final fuse: out = x + xn + sig(gl + b) * (gnh - xn) -------
__global__ __launch_bounds__(256) void final_kernel(
    const float* __restrict__ x, const float* __restrict__ xn,
    const float* __restrict__ gnh, const float* __restrict__ gl,
    const float* __restrict__ bhf, float* __restrict__ out)
{
    size_t i = (size_t)blockIdx.x * blockDim.x + threadIdx.x;  // float4 idx
    if (i >= (size_t)MROWS * DIM / 4) return;
    float4 xv = ((const float4*)x)[i];
    float4 nx = ((const float4*)xn)[i];
    float4 nv = ((const float4*)gnh)[i];
    float4 lv = ((const float4*)gl)[i];
    float4 bv = ((const float4*)bhf)[i & 127];
    float4 o;
    o.x = xv.x + nx.x + (nv.x - nx.x) / (1.f + expf(-(lv.x + bv.x)));
    o.y = xv.y + nx.y + (nv.y - nx.y) / (1.f + expf(-(lv.y + bv.y)));
    o.z = xv.z + nx.z + (nv.z - nx.z) / (1.f + expf(-(lv.z + bv.z)));
    o.w = xv.w + nx.w + (nv.w - nx.w) / (1.f + expf(-(lv.w + bv.w)));
    ((float4*)out)[i] = o;
}

// ---------------- host -------------------------------------------------------
extern "C" void kernel_launch(void* const* d_in, const int* in_sizes, int n_in,
                              void* d_out, int out_size)
{
    (void)in_sizes; (void)n_in; (void)out_size;
    const float* x      = (const float*)d_in[0];
    const float* gamma  = (const float*)d_in[1];
    const float* g_Wn   = (const float*)d_in[2];
    const float* g_Wif  = (const float*)d_in[3];
    const float* g_Whf  = (const float*)d_in[4];
    const float* g_bhf  = (const float*)d_in[5];
    const float* l0_Wn  = (const float*)d_in[6];
    const float* l0_Wif = (const float*)d_in[7];
    const float* l0_Whf = (const float*)d_in[8];
    const float* l0_bhf = (const float*)d_in[9];
    const float* l1_Wn  = (const float*)d_in[10];
    const float* l1_Wif = (const float*)d_in[11];
    const float* l1_Whf = (const float*)d_in[12];
    const float* l1_bhf = (const float*)d_in[13];
    float* out = (float*)d_out;

    float *S0, *S1, *S2, *S3;
    cudaGetSymbolAddress((void**)&S0, g_S0);
    cudaGetSymbolAddress((void**)&S1, g_S1);
    cudaGetSymbolAddress((void**)&S2, g_S2);
    cudaGetSymbolAddress((void**)&S3, g_S3);

    dim3 gg(4, 512);  // N tiles x M tiles

    rmsnorm_kernel<<<MROWS, 128>>>(x, gamma, S0);

    gemm512<<<gg, 256>>>(S0, l0_Wn,  S1, 1, 0);      // nh0 = tanh(xn @ Wn0)
    gemm512<<<gg, 256>>>(S0, l0_Wif, S2, 0, 0);      // if0 = xn @ Wif0
    lru_scan<<<128, 512>>>(S1, S2, l0_Whf, l0_bhf, S3);   // h0

    gemm512<<<gg, 256>>>(S3, l1_Wn,  S1, 1, 0);      // nh1 = tanh(h0 @ Wn1)
    gemm512<<<gg, 256>>>(S3, l1_Wif, S2, 0, 0);      // if1 = h0 @ Wif1
    lru_scan<<<128, 512>>>(S1, S2, l1_Whf, l1_bhf, S3);   // h1

    gemm512<<<gg, 256>>>(S3, g_Wn,  S1, 1, 0);       // gnh = tanh(h1 @ gWn)
    gemm512<<<gg, 256>>>(S0, g_Whf, S2, 0, 0);       // gl  = xn @ gWhf
    gemm512<<<gg, 256>>>(S3, g_Wif, S2, 0, 1);       // gl += h1 @ gWif

    final_kernel<<<32768, 256>>>(x, S0, S1, S2, g_bhf, out);
}

// round 4
// speedup vs baseline: 1.4910x; 1.4910x over previous
#include <cuda_runtime.h>
#include <cstdint>
#include <math.h>

#define DIM   512
#define BATCH 32
#define TLEN  2048
#define MROWS (BATCH * TLEN)

typedef unsigned long long u64;
typedef unsigned int u32;

// ---------------- scratch (device globals; no allocation allowed) ----------
__device__ float g_S0[(size_t)MROWS * DIM];  // xn
__device__ float g_S1[(size_t)MROWS * DIM];  // nh / gnh
__device__ float g_S2[(size_t)MROWS * DIM];  // ifg / gate logits
__device__ float g_S3[(size_t)MROWS * DIM];  // h (layer outputs)

// ---------------- f32x2 helpers -------------------------------------------
__device__ __forceinline__ u64 pk2(float x, float y) {
    u64 r; asm("mov.b64 %0, {%1,%2};" : "=l"(r) : "f"(x), "f"(y)); return r;
}
__device__ __forceinline__ float2 up2(u64 v) {
    float2 r; asm("mov.b64 {%0,%1}, %2;" : "=f"(r.x), "=f"(r.y) : "l"(v)); return r;
}
#define FMA2(d, a, b) asm("fma.rn.f32x2 %0, %1, %2, %0;" : "+l"(d) : "l"(a), "l"(b))

__device__ __forceinline__ u32 s2u(const void* p) {
    u32 a;
    asm("{ .reg .u64 t; cvta.to.shared.u64 t, %1; cvt.u32.u64 %0, t; }" : "=r"(a) : "l"(p));
    return a;
}
#define CLUSTER_SYNC() do { \
    asm volatile("barrier.cluster.arrive.aligned;" ::: "memory"); \
    asm volatile("barrier.cluster.wait.aligned;" ::: "memory"); \
} while (0)

// ---------------- rmsnorm ---------------------------------------------------
__global__ __launch_bounds__(128) void rmsnorm_kernel(
    const float* __restrict__ x, const float* __restrict__ gamma,
    float* __restrict__ xn)
{
    const size_t row = blockIdx.x;
    const int tid = threadIdx.x;
    float4 v = ((const float4*)(x + row * DIM))[tid];
    float ss = v.x * v.x + v.y * v.y + v.z * v.z + v.w * v.w;
    #pragma unroll
    for (int o = 16; o; o >>= 1) ss += __shfl_xor_sync(0xffffffffu, ss, o);
    __shared__ float sred[4];
    if ((tid & 31) == 0) sred[tid >> 5] = ss;
    __syncthreads();
    float tot = sred[0] + sred[1] + sred[2] + sred[3];
    float n = fmaxf(sqrtf(tot), 1e-12f);
    float s = 22.62741699796952f / n;  // sqrt(512)
    float4 gv = ((const float4*)gamma)[tid];
    float4 o;
    o.x = v.x * s * (gv.x + 1.f);
    o.y = v.y * s * (gv.y + 1.f);
    o.z = v.z * s * (gv.z + 1.f);
    o.w = v.w * s * (gv.w + 1.f);
    ((float4*)(xn + row * DIM))[tid] = o;
}

// ---------------- SGEMM (f32x2), C[M,512] = act(A[M,512] @ W[512,512]) ------
// 128x128 tile, BK=16, 256 threads, 8x8 per thread.
__global__ __launch_bounds__(256, 2) void gemm512(
    const float* __restrict__ A, const float* __restrict__ W,
    float* __restrict__ C, int act, int accum)
{
    __shared__ __align__(16) float As[16][132];
    __shared__ __align__(16) float Bs[16][132];
    const int tid = threadIdx.x;
    const int tx = tid & 15, ty = tid >> 4;
    const size_t m0 = (size_t)blockIdx.y * 128;
    const int n0 = blockIdx.x * 128;

    u64 acc[8][4];
    #pragma unroll
    for (int i = 0; i < 8; i++)
        #pragma unroll
        for (int jj = 0; jj < 4; jj++) acc[i][jj] = 0ull;

    const int ar = tid >> 2, ac4 = (tid & 3) * 4;
    const int br = tid >> 4, bc4 = (tid & 15) * 4;

    for (int kt = 0; kt < 512; kt += 16) {
        float4 a0 = *(const float4*)(A + (m0 + ar) * 512 + kt + ac4);
        float4 a1 = *(const float4*)(A + (m0 + ar + 64) * 512 + kt + ac4);
        float4 b0 = *(const float4*)(W + (size_t)(kt + br) * 512 + n0 + bc4);
        float4 b1 = *(const float4*)(W + (size_t)(kt + br) * 512 + n0 + bc4 + 64);
        __syncthreads();
        As[ac4 + 0][ar] = a0.x; As[ac4 + 1][ar] = a0.y;
        As[ac4 + 2][ar] = a0.z; As[ac4 + 3][ar] = a0.w;
        As[ac4 + 0][ar + 64] = a1.x; As[ac4 + 1][ar + 64] = a1.y;
        As[ac4 + 2][ar + 64] = a1.z; As[ac4 + 3][ar + 64] = a1.w;
        *(float4*)&Bs[br][bc4] = b0;
        *(float4*)&Bs[br][bc4 + 64] = b1;
        __syncthreads();
        #pragma unroll
        for (int k = 0; k < 16; k++) {
            float4 fa0 = *(const float4*)&As[k][ty * 4];
            float4 fa1 = *(const float4*)&As[k][ty * 4 + 64];
            // read B pairs directly as packed u64 (bit-identical to pk2 repack)
            ulonglong2 b0q = *(const ulonglong2*)&Bs[k][tx * 4];
            ulonglong2 b1q = *(const ulonglong2*)&Bs[k][tx * 4 + 64];
            u64 bp0 = b0q.x, bp1 = b0q.y, bp2 = b1q.x, bp3 = b1q.y;
            float av[8] = {fa0.x, fa0.y, fa0.z, fa0.w, fa1.x, fa1.y, fa1.z, fa1.w};
            #pragma unroll
            for (int i = 0; i < 8; i++) {
                u64 ad = pk2(av[i], av[i]);
                FMA2(acc[i][0], ad, bp0);
                FMA2(acc[i][1], ad, bp1);
                FMA2(acc[i][2], ad, bp2);
                FMA2(acc[i][3], ad, bp3);
            }
        }
    }
    #pragma unroll
    for (int i = 0; i < 8; i++) {
        int row = (i < 4) ? (ty * 4 + i) : (64 + ty * 4 + (i - 4));
        float* cp = C + (m0 + row) * 512 + n0;
        #pragma unroll
        for (int jh = 0; jh < 2; jh++) {
            float2 v0 = up2(acc[i][jh * 2]);
            float2 v1 = up2(acc[i][jh * 2 + 1]);
            float4 v = make_float4(v0.x, v0.y, v1.x, v1.y);
            if (act) {
                v.x = tanhf(v.x); v.y = tanhf(v.y);
                v.z = tanhf(v.z); v.w = tanhf(v.w);
            }
            int col = jh * 64 + tx * 4;
            if (accum) {
                float4 o = *(float4*)(cp + col);
                v.x += o.x; v.y += o.y; v.z += o.z; v.w += o.w;
            }
            *(float4*)(cp + col) = v;
        }
    }
}

// ---------------- LRU recurrence -------------------------------------------
// One cluster of 8 CTAs handles 2 batches; each CTA owns 64 output columns,
// Whf columns live in registers. Thread (jl = tid>>3, s = tid&7): output
// j = crank*64 + jl, k-slice s. Dot reduced over s via shfl.bfly; new h
// broadcast to all 8 CTAs via DSMEM, double-buffered, one cluster.sync/step.
//
// R3 change: nh/ifg for step t+1 are loaded by 64 loader threads as float4
// (64 LDG.128/CTA/step instead of 2048 redundant LDG.32) and staged through
// smem (double-buffered); gate threads read them back as broadcast LDS.
__global__ void __cluster_dims__(8, 1, 1) __launch_bounds__(512, 1)
lru_scan(const float* __restrict__ nh, const float* __restrict__ ifg,
         const float* __restrict__ Whf, const float* __restrict__ bhf,
         float* __restrict__ hout)
{
    __shared__ __align__(16) float hbuf[2][2][DIM];   // [buffer][batch][j]
    __shared__ __align__(16) float stage[2][4][64];   // [buffer][nh0,if0,nh1,if1][jl]
    const u32 tid = threadIdx.x;
    const u32 jl = tid >> 3, s = tid & 7;
    u32 crank; asm("mov.u32 %0, %%cluster_ctarank;" : "=r"(crank));
    const u32 j = crank * 64 + jl;
    const u32 cl = blockIdx.x >> 3;

    // weights, packed + rotated so smem h reads are conflict-free
    u64 wp[32];
    #pragma unroll
    for (int ii = 0; ii < 16; ii++) {
        u32 i4 = (ii + s) & 15;
        u32 k = s * 64 + i4 * 4;
        float w0 = Whf[(size_t)(k + 0) * DIM + j];
        float w1 = Whf[(size_t)(k + 1) * DIM + j];
        float w2 = Whf[(size_t)(k + 2) * DIM + j];
        float w3 = Whf[(size_t)(k + 3) * DIM + j];
        wp[2 * ii] = pk2(w0, w1);
        wp[2 * ii + 1] = pk2(w2, w3);
    }
    const float bias = bhf[j];

    hbuf[0][0][tid] = 0.f;
    hbuf[0][1][tid] = 0.f;

    u32 a00 = s2u(&hbuf[0][0][j]), a01 = s2u(&hbuf[0][1][j]);
    u32 a10 = s2u(&hbuf[1][0][j]), a11 = s2u(&hbuf[1][1][j]);
    u32 r00, r01, r10, r11;
    asm("mapa.shared::cluster.u32 %0, %1, %2;" : "=r"(r00) : "r"(a00), "r"(s));
    asm("mapa.shared::cluster.u32 %0, %1, %2;" : "=r"(r01) : "r"(a01), "r"(s));
    asm("mapa.shared::cluster.u32 %0, %1, %2;" : "=r"(r10) : "r"(a10), "r"(s));
    asm("mapa.shared::cluster.u32 %0, %1, %2;" : "=r"(r11) : "r"(a11), "r"(s));

    // loader threads: tid<64, sel = which of {nh_b0, ifg_b0, nh_b1, ifg_b1},
    // f4 = which float4 of the CTA's 64-column slice.
    const u32 sel = tid >> 4;
    const u32 f4 = tid & 15;
    const float* lp = nullptr;
    if (tid < 64) {
        const float* arr = (sel & 1) ? ifg : nh;
        u32 b = sel >> 1;
        lp = arr + ((size_t)(cl * 2 + b) * TLEN) * DIM + crank * 64 + f4 * 4;
        float4 v = *(const float4*)lp;          // t = 0
        *(float4*)&stage[0][sel][f4 * 4] = v;
    }

    const size_t obase0 = ((size_t)(cl * 2 + 0) * TLEN) * DIM + j;
    const size_t obase1 = ((size_t)(cl * 2 + 1) * TLEN) * DIM + j;

    __syncthreads();
    CLUSTER_SYNC();

    float h0 = 0.f, h1 = 0.f;
    int p = 0;
    for (int t = 0; t < TLEN; t++) {
        const int sb = t & 1;
        // prefetch step t+1 operands (latency overlapped with the FMA loop)
        float4 pv;
        const bool do_pref = (tid < 64) && (t + 1 < TLEN);
        if (do_pref) pv = *(const float4*)(lp + (size_t)(t + 1) * DIM);

        const ulonglong2* hq0 = (const ulonglong2*)hbuf[p][0];
        const ulonglong2* hq1 = (const ulonglong2*)hbuf[p][1];
        u64 acc0a = 0ull, acc0b = 0ull, acc1a = 0ull, acc1b = 0ull;
        #pragma unroll
        for (int ii = 0; ii < 16; ii++) {
            u32 idx = s * 16 + ((ii + s) & 15);
            ulonglong2 hv0 = hq0[idx];
            ulonglong2 hv1 = hq1[idx];
            FMA2(acc0a, wp[2 * ii], hv0.x);
            FMA2(acc0b, wp[2 * ii + 1], hv0.y);
            FMA2(acc1a, wp[2 * ii], hv1.x);
            FMA2(acc1b, wp[2 * ii + 1], hv1.y);
        }
        float2 u0 = up2(acc0a), u0b = up2(acc0b);
        float2 u1 = up2(acc1a), u1b = up2(acc1b);
        float d0 = (u0.x + u0.y) + (u0b.x + u0b.y);
        float d1 = (u1.x + u1.y) + (u1b.x + u1b.y);
        d0 += __shfl_xor_sync(0xffffffffu, d0, 1);
        d0 += __shfl_xor_sync(0xffffffffu, d0, 2);
        d0 += __shfl_xor_sync(0xffffffffu, d0, 4);
        d1 += __shfl_xor_sync(0xffffffffu, d1, 1);
        d1 += __shfl_xor_sync(0xffffffffu, d1, 2);
        d1 += __shfl_xor_sync(0xffffffffu, d1, 4);

        const float nv0 = stage[sb][0][jl], iv0 = stage[sb][1][jl];
        const float nv1 = stage[sb][2][jl], iv1 = stage[sb][3][jl];

        float g0 = 1.f / (1.f + expf(-(d0 + bias + iv0)));
        float g1 = 1.f / (1.f + expf(-(d1 + bias + iv1)));
        float hn0 = fmaf(g0, nv0 - h0, h0);
        float hn1 = fmaf(g1, nv1 - h1, h1);
        h0 = hn0; h1 = hn1;

        u32 d0a = p ? r00 : r10;  // write buffer p^1
        u32 d1a = p ? r01 : r11;
        asm volatile("st.shared::cluster.f32 [%0], %1;" :: "r"(d0a), "f"(hn0) : "memory");
        asm volatile("st.shared::cluster.f32 [%0], %1;" :: "r"(d1a), "f"(hn1) : "memory");
        if (s == 0) {
            hout[obase0 + (size_t)t * DIM] = hn0;
            hout[obase1 + (size_t)t * DIM] = hn1;
        }
        if (do_pref) *(float4*)&stage[sb ^ 1][sel][f4 * 4] = pv;
        CLUSTER_SYNC();
        p ^= 1;
    }
}

// ---------------- final fuse: out = x + xn + sig(gl + b) * (gnh - xn) -------
__global__ __launch_bounds__(256) void final_kernel(
    const float* __restrict__ x, const float* __restrict__ xn,
    const float* __restrict__ gnh, const float* __restrict__ gl,
    const float* __restrict__ bhf, float* __restrict__ out)
{
    size_t i = (size_t)blockIdx.x * blockDim.x + threadIdx.x;  // float4 idx
    if (i >= (size_t)MROWS * DIM / 4) return;
    float4 xv = ((const float4*)x)[i];
    float4 nx = ((const float4*)xn)[i];
    float4 nv = ((const float4*)gnh)[i];
    float4 lv = ((const float4*)gl)[i];
    float4 bv = ((const float4*)bhf)[i & 127];
    float4 o;
    o.x = xv.x + nx.x + (nv.x - nx.x) / (1.f + expf(-(lv.x + bv.x)));
    o.y = xv.y + nx.y + (nv.y - nx.y) / (1.f + expf(-(lv.y + bv.y)));
    o.z = xv.z + nx.z + (nv.z - nx.z) / (1.f + expf(-(lv.z + bv.z)));
    o.w = xv.w + nx.w + (nv.w - nx.w) / (1.f + expf(-(lv.w + bv.w)));
    ((float4*)out)[i] = o;
}

// ---------------- host -------------------------------------------------------
extern "C" void kernel_launch(void* const* d_in, const int* in_sizes, int n_in,
                              void* d_out, int out_size)
{
    (void)in_sizes; (void)n_in; (void)out_size;
    const float* x      = (const float*)d_in[0];
    const float* gamma  = (const float*)d_in[1];
    const float* g_Wn   = (const float*)d_in[2];
    const float* g_Wif  = (const float*)d_in[3];
    const float* g_Whf  = (const float*)d_in[4];
    const float* g_bhf  = (const float*)d_in[5];
    const float* l0_Wn  = (const float*)d_in[6];
    const float* l0_Wif = (const float*)d_in[7];
    const float* l0_Whf = (const float*)d_in[8];
    const float* l0_bhf = (const float*)d_in[9];
    const float* l1_Wn  = (const float*)d_in[10];
    const float* l1_Wif = (const float*)d_in[11];
    const float* l1_Whf = (const float*)d_in[12];
    const float* l1_bhf = (const float*)d_in[13];
    float* out = (float*)d_out;

    float *S0, *S1, *S2, *S3;
    cudaGetSymbolAddress((void**)&S0, g_S0);
    cudaGetSymbolAddress((void**)&S1, g_S1);
    cudaGetSymbolAddress((void**)&S2, g_S2);
    cudaGetSymbolAddress((void**)&S3, g_S3);

    dim3 gg(4, 512);  // N tiles x M tiles

    rmsnorm_kernel<<<MROWS, 128>>>(x, gamma, S0);

    gemm512<<<gg, 256>>>(S0, l0_Wn,  S1, 1, 0);           // nh0 = tanh(xn @ Wn0)
    gemm512<<<gg, 256>>>(S0, l0_Wif, S2, 0, 0);           // if0 = xn @ Wif0
    lru_scan<<<128, 512>>>(S1, S2, l0_Whf, l0_bhf, S3);   // h0

    gemm512<<<gg, 256>>>(S3, l1_Wn,  S1, 1, 0);           // nh1 = tanh(h0 @ Wn1)
    gemm512<<<gg, 256>>>(S3, l1_Wif, S2, 0, 0);           // if1 = h0 @ Wif1
    lru_scan<<<128, 512>>>(S1, S2, l1_Whf, l1_bhf, S3);   // h1

    gemm512<<<gg, 256>>>(S3, g_Wn,  S1, 1, 0);            // gnh = tanh(h1 @ gWn)
    gemm512<<<gg, 256>>>(S0, g_Whf, S2, 0, 0);            // gl  = xn @ gWhf
    gemm512<<<gg, 256>>>(S3, g_Wif, S2, 0, 1);            // gl += h1 @ gWif

    final_kernel<<<32768, 256>>>(x, S0, S1, S2, g_bhf, out);
}

// round 9
// speedup vs baseline: 1.5679x; 1.0516x over previous
#include <cuda_runtime.h>
#include <cstdint>
#include <math.h>

#define DIM   512
#define BATCH 32
#define TLEN  2048
#define MROWS (BATCH * TLEN)

typedef unsigned long long u64;
typedef unsigned int u32;

// ---------------- scratch (device globals; no allocation allowed) ----------
__device__ float g_S0[(size_t)MROWS * DIM];  // xn
__device__ float g_S1[(size_t)MROWS * DIM];  // nh / gnh
__device__ float g_S2[(size_t)MROWS * DIM];  // ifg / gate logits
__device__ float g_S3[(size_t)MROWS * DIM];  // h (layer outputs)

// ---------------- f32x2 helpers -------------------------------------------
__device__ __forceinline__ u64 pk2(float x, float y) {
    u64 r; asm("mov.b64 %0, {%1,%2};" : "=l"(r) : "f"(x), "f"(y)); return r;
}
__device__ __forceinline__ float2 up2(u64 v) {
    float2 r; asm("mov.b64 {%0,%1}, %2;" : "=f"(r.x), "=f"(r.y) : "l"(v)); return r;
}
#define FMA2(d, a, b) asm("fma.rn.f32x2 %0, %1, %2, %0;" : "+l"(d) : "l"(a), "l"(b))

__device__ __forceinline__ u32 s2u(const void* p) {
    u32 a;
    asm("{ .reg .u64 t; cvta.to.shared.u64 t, %1; cvt.u32.u64 %0, t; }" : "=r"(a) : "l"(p));
    return a;
}
#define CLUSTER_SYNC() do { \
    asm volatile("barrier.cluster.arrive.aligned;" ::: "memory"); \
    asm volatile("barrier.cluster.wait.aligned;" ::: "memory"); \
} while (0)

// ---------------- rmsnorm ---------------------------------------------------
__global__ __launch_bounds__(128) void rmsnorm_kernel(
    const float* __restrict__ x, const float* __restrict__ gamma,
    float* __restrict__ xn)
{
    const size_t row = blockIdx.x;
    const int tid = threadIdx.x;
    float4 v = ((const float4*)(x + row * DIM))[tid];
    float ss = v.x * v.x + v.y * v.y + v.z * v.z + v.w * v.w;
    #pragma unroll
    for (int o = 16; o; o >>= 1) ss += __shfl_xor_sync(0xffffffffu, ss, o);
    __shared__ float sred[4];
    if ((tid & 31) == 0) sred[tid >> 5] = ss;
    __syncthreads();
    float tot = sred[0] + sred[1] + sred[2] + sred[3];
    float n = fmaxf(sqrtf(tot), 1e-12f);
    float s = 22.62741699796952f / n;  // sqrt(512)
    float4 gv = ((const float4*)gamma)[tid];
    float4 o;
    o.x = v.x * s * (gv.x + 1.f);
    o.y = v.y * s * (gv.y + 1.f);
    o.z = v.z * s * (gv.z + 1.f);
    o.w = v.w * s * (gv.w + 1.f);
    ((float4*)(xn + row * DIM))[tid] = o;
}

// ---------------- SGEMM (f32x2), C[M,512] = act(A[M,512] @ W[512,512]) ------
// 128x128 tile, BK=16, 256 threads, 8x8 per thread.
// R5: double-buffered smem with register-staged prefetch, one sync per tile.
__device__ __forceinline__ void compute16(
    const float (&As)[16][132], const float (&Bs)[16][132],
    int tx, int ty, u64 (&acc)[8][4])
{
    #pragma unroll
    for (int k = 0; k < 16; k++) {
        float4 fa0 = *(const float4*)&As[k][ty * 4];
        float4 fa1 = *(const float4*)&As[k][ty * 4 + 64];
        ulonglong2 b0q = *(const ulonglong2*)&Bs[k][tx * 4];
        ulonglong2 b1q = *(const ulonglong2*)&Bs[k][tx * 4 + 64];
        u64 bp0 = b0q.x, bp1 = b0q.y, bp2 = b1q.x, bp3 = b1q.y;
        float av[8] = {fa0.x, fa0.y, fa0.z, fa0.w, fa1.x, fa1.y, fa1.z, fa1.w};
        #pragma unroll
        for (int i = 0; i < 8; i++) {
            u64 ad = pk2(av[i], av[i]);
            FMA2(acc[i][0], ad, bp0);
            FMA2(acc[i][1], ad, bp1);
            FMA2(acc[i][2], ad, bp2);
            FMA2(acc[i][3], ad, bp3);
        }
    }
}

__global__ __launch_bounds__(256, 2) void gemm512(
    const float* __restrict__ A, const float* __restrict__ W,
    float* __restrict__ C, int act, int accum)
{
    __shared__ __align__(16) float As[2][16][132];
    __shared__ __align__(16) float Bs[2][16][132];
    const int tid = threadIdx.x;
    const int tx = tid & 15, ty = tid >> 4;
    const size_t m0 = (size_t)blockIdx.y * 128;
    const int n0 = blockIdx.x * 128;

    u64 acc[8][4];
    #pragma unroll
    for (int i = 0; i < 8; i++)
        #pragma unroll
        for (int jj = 0; jj < 4; jj++) acc[i][jj] = 0ull;

    const int ar = tid >> 2, ac4 = (tid & 3) * 4;
    const int br = tid >> 4, bc4 = (tid & 15) * 4;

    const float* Ap0 = A + (m0 + ar) * 512 + ac4;
    const float* Ap1 = A + (m0 + ar + 64) * 512 + ac4;
    const float* Wp0 = W + (size_t)br * 512 + n0 + bc4;
    const float* Wp1 = Wp0 + 64;

    // load tile 0 into buffer 0
    {
        float4 a0 = *(const float4*)Ap0;
        float4 a1 = *(const float4*)Ap1;
        float4 b0 = *(const float4*)Wp0;
        float4 b1 = *(const float4*)Wp1;
        As[0][ac4 + 0][ar] = a0.x; As[0][ac4 + 1][ar] = a0.y;
        As[0][ac4 + 2][ar] = a0.z; As[0][ac4 + 3][ar] = a0.w;
        As[0][ac4 + 0][ar + 64] = a1.x; As[0][ac4 + 1][ar + 64] = a1.y;
        As[0][ac4 + 2][ar + 64] = a1.z; As[0][ac4 + 3][ar + 64] = a1.w;
        *(float4*)&Bs[0][br][bc4] = b0;
        *(float4*)&Bs[0][br][bc4 + 64] = b1;
    }
    __syncthreads();

    int p = 0;
    for (int kt = 16; kt < 512; kt += 16) {
        // prefetch tile kt into registers (covered by the compute below)
        float4 a0 = *(const float4*)(Ap0 + kt);
        float4 a1 = *(const float4*)(Ap1 + kt);
        float4 b0 = *(const float4*)(Wp0 + (size_t)kt * 512);
        float4 b1 = *(const float4*)(Wp1 + (size_t)kt * 512);

        compute16(As[p], Bs[p], tx, ty, acc);

        const int q = p ^ 1;
        As[q][ac4 + 0][ar] = a0.x; As[q][ac4 + 1][ar] = a0.y;
        As[q][ac4 + 2][ar] = a0.z; As[q][ac4 + 3][ar] = a0.w;
        As[q][ac4 + 0][ar + 64] = a1.x; As[q][ac4 + 1][ar + 64] = a1.y;
        As[q][ac4 + 2][ar + 64] = a1.z; As[q][ac4 + 3][ar + 64] = a1.w;
        *(float4*)&Bs[q][br][bc4] = b0;
        *(float4*)&Bs[q][br][bc4 + 64] = b1;
        __syncthreads();
        p = q;
    }
    compute16(As[p], Bs[p], tx, ty, acc);

    #pragma unroll
    for (int i = 0; i < 8; i++) {
        int row = (i < 4) ? (ty * 4 + i) : (64 + ty * 4 + (i - 4));
        float* cp = C + (m0 + row) * 512 + n0;
        #pragma unroll
        for (int jh = 0; jh < 2; jh++) {
            float2 v0 = up2(acc[i][jh * 2]);
            float2 v1 = up2(acc[i][jh * 2 + 1]);
            float4 v = make_float4(v0.x, v0.y, v1.x, v1.y);
            if (act) {
                v.x = tanhf(v.x); v.y = tanhf(v.y);
                v.z = tanhf(v.z); v.w = tanhf(v.w);
            }
            int col = jh * 64 + tx * 4;
            if (accum) {
                float4 o = *(float4*)(cp + col);
                v.x += o.x; v.y += o.y; v.z += o.z; v.w += o.w;
            }
            *(float4*)(cp + col) = v;
        }
    }
}

// ---------------- LRU recurrence (unchanged from R3) ------------------------
__global__ void __cluster_dims__(8, 1, 1) __launch_bounds__(512, 1)
lru_scan(const float* __restrict__ nh, const float* __restrict__ ifg,
         const float* __restrict__ Whf, const float* __restrict__ bhf,
         float* __restrict__ hout)
{
    __shared__ __align__(16) float hbuf[2][2][DIM];   // [buffer][batch][j]
    __shared__ __align__(16) float stage[2][4][64];   // [buffer][nh0,if0,nh1,if1][jl]
    const u32 tid = threadIdx.x;
    const u32 jl = tid >> 3, s = tid & 7;
    u32 crank; asm("mov.u32 %0, %%cluster_ctarank;" : "=r"(crank));
    const u32 j = crank * 64 + jl;
    const u32 cl = blockIdx.x >> 3;

    // weights, packed + rotated so smem h reads are conflict-free
    u64 wp[32];
    #pragma unroll
    for (int ii = 0; ii < 16; ii++) {
        u32 i4 = (ii + s) & 15;
        u32 k = s * 64 + i4 * 4;
        float w0 = Whf[(size_t)(k + 0) * DIM + j];
        float w1 = Whf[(size_t)(k + 1) * DIM + j];
        float w2 = Whf[(size_t)(k + 2) * DIM + j];
        float w3 = Whf[(size_t)(k + 3) * DIM + j];
        wp[2 * ii] = pk2(w0, w1);
        wp[2 * ii + 1] = pk2(w2, w3);
    }
    const float bias = bhf[j];

    hbuf[0][0][tid] = 0.f;
    hbuf[0][1][tid] = 0.f;

    u32 a00 = s2u(&hbuf[0][0][j]), a01 = s2u(&hbuf[0][1][j]);
    u32 a10 = s2u(&hbuf[1][0][j]), a11 = s2u(&hbuf[1][1][j]);
    u32 r00, r01, r10, r11;
    asm("mapa.shared::cluster.u32 %0, %1, %2;" : "=r"(r00) : "r"(a00), "r"(s));
    asm("mapa.shared::cluster.u32 %0, %1, %2;" : "=r"(r01) : "r"(a01), "r"(s));
    asm("mapa.shared::cluster.u32 %0, %1, %2;" : "=r"(r10) : "r"(a10), "r"(s));
    asm("mapa.shared::cluster.u32 %0, %1, %2;" : "=r"(r11) : "r"(a11), "r"(s));

    const u32 sel = tid >> 4;
    const u32 f4 = tid & 15;
    const float* lp = nullptr;
    if (tid < 64) {
        const float* arr = (sel & 1) ? ifg : nh;
        u32 b = sel >> 1;
        lp = arr + ((size_t)(cl * 2 + b) * TLEN) * DIM + crank * 64 + f4 * 4;
        float4 v = *(const float4*)lp;          // t = 0
        *(float4*)&stage[0][sel][f4 * 4] = v;
    }

    const size_t obase0 = ((size_t)(cl * 2 + 0) * TLEN) * DIM + j;
    const size_t obase1 = ((size_t)(cl * 2 + 1) * TLEN) * DIM + j;

    __syncthreads();
    CLUSTER_SYNC();

    float h0 = 0.f, h1 = 0.f;
    int p = 0;
    for (int t = 0; t < TLEN; t++) {
        const int sb = t & 1;
        float4 pv;
        const bool do_pref = (tid < 64) && (t + 1 < TLEN);
        if (do_pref) pv = *(const float4*)(lp + (size_t)(t + 1) * DIM);

        const ulonglong2* hq0 = (const ulonglong2*)hbuf[p][0];
        const ulonglong2* hq1 = (const ulonglong2*)hbuf[p][1];
        u64 acc0a = 0ull, acc0b = 0ull, acc1a = 0ull, acc1b = 0ull;
        #pragma unroll
        for (int ii = 0; ii < 16; ii++) {
            u32 idx = s * 16 + ((ii + s) & 15);
            ulonglong2 hv0 = hq0[idx];
            ulonglong2 hv1 = hq1[idx];
            FMA2(acc0a, wp[2 * ii], hv0.x);
            FMA2(acc0b, wp[2 * ii + 1], hv0.y);
            FMA2(acc1a, wp[2 * ii], hv1.x);
            FMA2(acc1b, wp[2 * ii + 1], hv1.y);
        }
        float2 u0 = up2(acc0a), u0b = up2(acc0b);
        float2 u1 = up2(acc1a), u1b = up2(acc1b);
        float d0 = (u0.x + u0.y) + (u0b.x + u0b.y);
        float d1 = (u1.x + u1.y) + (u1b.x + u1b.y);
        d0 += __shfl_xor_sync(0xffffffffu, d0, 1);
        d0 += __shfl_xor_sync(0xffffffffu, d0, 2);
        d0 += __shfl_xor_sync(0xffffffffu, d0, 4);
        d1 += __shfl_xor_sync(0xffffffffu, d1, 1);
        d1 += __shfl_xor_sync(0xffffffffu, d1, 2);
        d1 += __shfl_xor_sync(0xffffffffu, d1, 4);

        const float nv0 = stage[sb][0][jl], iv0 = stage[sb][1][jl];
        const float nv1 = stage[sb][2][jl], iv1 = stage[sb][3][jl];

        float g0 = 1.f / (1.f + expf(-(d0 + bias + iv0)));
        float g1 = 1.f / (1.f + expf(-(d1 + bias + iv1)));
        float hn0 = fmaf(g0, nv0 - h0, h0);
        float hn1 = fmaf(g1, nv1 - h1, h1);
        h0 = hn0; h1 = hn1;

        u32 d0a = p ? r00 : r10;  // write buffer p^1
        u32 d1a = p ? r01 : r11;
        asm volatile("st.shared::cluster.f32 [%0], %1;" :: "r"(d0a), "f"(hn0) : "memory");
        asm volatile("st.shared::cluster.f32 [%0], %1;" :: "r"(d1a), "f"(hn1) : "memory");
        if (s == 0) {
            hout[obase0 + (size_t)t * DIM] = hn0;
            hout[obase1 + (size_t)t * DIM] = hn1;
        }
        if (do_pref) *(float4*)&stage[sb ^ 1][sel][f4 * 4] = pv;
        CLUSTER_SYNC();
        p ^= 1;
    }
}

// ---------------- final fuse: out = x + xn + sig(gl + b) * (gnh - xn) -------
__global__ __launch_bounds__(256) void final_kernel(
    const float* __restrict__ x, const float* __restrict__ xn,
    const float* __restrict__ gnh, const float* __restrict__ gl,
    const float* __restrict__ bhf, float* __restrict__ out)
{
    size_t i = (size_t)blockIdx.x * blockDim.x + threadIdx.x;  // float4 idx
    if (i >= (size_t)MROWS * DIM / 4) return;
    float4 xv = ((const float4*)x)[i];
    float4 nx = ((const float4*)xn)[i];
    float4 nv = ((const float4*)gnh)[i];
    float4 lv = ((const float4*)gl)[i];
    float4 bv = ((const float4*)bhf)[i & 127];
    float4 o;
    o.x = xv.x + nx.x + (nv.x - nx.x) / (1.f + expf(-(lv.x + bv.x)));
    o.y = xv.y + nx.y + (nv.y - nx.y) / (1.f + expf(-(lv.y + bv.y)));
    o.z = xv.z + nx.z + (nv.z - nx.z) / (1.f + expf(-(lv.z + bv.z)));
    o.w = xv.w + nx.w + (nv.w - nx.w) / (1.f + expf(-(lv.w + bv.w)));
    ((float4*)out)[i] = o;
}

// ---------------- host -------------------------------------------------------
extern "C" void kernel_launch(void* const* d_in, const int* in_sizes, int n_in,
                              void* d_out, int out_size)
{
    (void)in_sizes; (void)n_in; (void)out_size;
    const float* x      = (const float*)d_in[0];
    const float* gamma  = (const float*)d_in[1];
    const float* g_Wn   = (const float*)d_in[2];
    const float* g_Wif  = (const float*)d_in[3];
    const float* g_Whf  = (const float*)d_in[4];
    const float* g_bhf  = (const float*)d_in[5];
    const float* l0_Wn  = (const float*)d_in[6];
    const float* l0_Wif = (const float*)d_in[7];
    const float* l0_Whf = (const float*)d_in[8];
    const float* l0_bhf = (const float*)d_in[9];
    const float* l1_Wn  = (const float*)d_in[10];
    const float* l1_Wif = (const float*)d_in[11];
    const float* l1_Whf = (const float*)d_in[12];
    const float* l1_bhf = (const float*)d_in[13];
    float* out = (float*)d_out;

    float *S0, *S1, *S2, *S3;
    cudaGetSymbolAddress((void**)&S0, g_S0);
    cudaGetSymbolAddress((void**)&S1, g_S1);
    cudaGetSymbolAddress((void**)&S2, g_S2);
    cudaGetSymbolAddress((void**)&S3, g_S3);

    dim3 gg(4, 512);  // N tiles x M tiles

    rmsnorm_kernel<<<MROWS, 128>>>(x, gamma, S0);

    gemm512<<<gg, 256>>>(S0, l0_Wn,  S1, 1, 0);           // nh0 = tanh(xn @ Wn0)
    gemm512<<<gg, 256>>>(S0, l0_Wif, S2, 0, 0);           // if0 = xn @ Wif0
    lru_scan<<<128, 512>>>(S1, S2, l0_Whf, l0_bhf, S3);   // h0

    gemm512<<<gg, 256>>>(S3, l1_Wn,  S1, 1, 0);           // nh1 = tanh(h0 @ Wn1)
    gemm512<<<gg, 256>>>(S3, l1_Wif, S2, 0, 0);           // if1 = h0 @ Wif1
    lru_scan<<<128, 512>>>(S1, S2, l1_Whf, l1_bhf, S3);   // h1

    gemm512<<<gg, 256>>>(S3, g_Wn,  S1, 1, 0);            // gnh = tanh(h1 @ gWn)
    gemm512<<<gg, 256>>>(S0, g_Whf, S2, 0, 0);            // gl  = xn @ gWhf
    gemm512<<<gg, 256>>>(S3, g_Wif, S2, 0, 1);            // gl += h1 @ gWif

    final_kernel<<<32768, 256>>>(x, S0, S1, S2, g_bhf, out);
}

// round 16
// speedup vs baseline: 1.7143x; 1.0934x over previous
#include <cuda_runtime.h>
#include <cuda_bf16.h>
#include <cstdint>
#include <math.h>

#define DIM   512
#define BATCH 32
#define TLEN  2048
#define MROWS (BATCH * TLEN)

typedef unsigned long long u64;
typedef unsigned int u32;

// ---------------- scratch (device globals; no allocation allowed) ----------
__device__ float g_S0[(size_t)MROWS * DIM];  // xn
__device__ float g_S1[(size_t)MROWS * DIM];  // nh / gnh
__device__ float g_S2[(size_t)MROWS * DIM];  // ifg / gate logits
__device__ float g_S3[(size_t)MROWS * DIM];  // h (layer outputs)
// transposed + hi/lo split weights (bf16), [widx][n*512 + k]
__device__ __nv_bfloat16 g_WTh[7][512 * 512];
__device__ __nv_bfloat16 g_WTl[7][512 * 512];

// ---------------- helpers ---------------------------------------------------
__device__ __forceinline__ u64 pk2(float x, float y) {
    u64 r; asm("mov.b64 %0, {%1,%2};" : "=l"(r) : "f"(x), "f"(y)); return r;
}
__device__ __forceinline__ float2 up2(u64 v) {
    float2 r; asm("mov.b64 {%0,%1}, %2;" : "=f"(r.x), "=f"(r.y) : "l"(v)); return r;
}
#define FMA2(d, a, b) asm("fma.rn.f32x2 %0, %1, %2, %0;" : "+l"(d) : "l"(a), "l"(b))

__device__ __forceinline__ u32 s2u(const void* p) {
    u32 a;
    asm("{ .reg .u64 t; cvta.to.shared.u64 t, %1; cvt.u32.u64 %0, t; }" : "=r"(a) : "l"(p));
    return a;
}
#define CLUSTER_SYNC() do { \
    asm volatile("barrier.cluster.arrive.aligned;" ::: "memory"); \
    asm volatile("barrier.cluster.wait.aligned;" ::: "memory"); \
} while (0)

__device__ __forceinline__ void ldsm4(u32& r0, u32& r1, u32& r2, u32& r3, u32 addr) {
    asm volatile("ldmatrix.sync.aligned.m8n8.x4.shared.b16 {%0,%1,%2,%3}, [%4];"
                 : "=r"(r0), "=r"(r1), "=r"(r2), "=r"(r3) : "r"(addr));
}
__device__ __forceinline__ void mma16816(float* c, const u32* a, const u32* b) {
    asm volatile(
        "mma.sync.aligned.m16n8k16.row.col.f32.bf16.bf16.f32 "
        "{%0,%1,%2,%3}, {%4,%5,%6,%7}, {%8,%9}, {%0,%1,%2,%3};"
        : "+f"(c[0]), "+f"(c[1]), "+f"(c[2]), "+f"(c[3])
        : "r"(a[0]), "r"(a[1]), "r"(a[2]), "r"(a[3]), "r"(b[0]), "r"(b[1]));
}

// split one float4 into hi/lo bf16 pairs (2x u32 each)
__device__ __forceinline__ void cvt_hilo(float4 v, u32& h01, u32& h23, u32& l01, u32& l23) {
    __nv_bfloat16 hx = __float2bfloat16(v.x), hy = __float2bfloat16(v.y);
    __nv_bfloat16 hz = __float2bfloat16(v.z), hw = __float2bfloat16(v.w);
    __nv_bfloat162 H0 = __halves2bfloat162(hx, hy), H1 = __halves2bfloat162(hz, hw);
    float lx = v.x - __bfloat162float(hx), ly = v.y - __bfloat162float(hy);
    float lz = v.z - __bfloat162float(hz), lw = v.w - __bfloat162float(hw);
    __nv_bfloat162 L0 = __floats2bfloat162_rn(lx, ly), L1 = __floats2bfloat162_rn(lz, lw);
    h01 = *(u32*)&H0; h23 = *(u32*)&H1;
    l01 = *(u32*)&L0; l23 = *(u32*)&L1;
}

// ---------------- weight prep: WT[n,k] = W[k,n], hi/lo bf16 split -----------
__global__ __launch_bounds__(1024) void prep_w(
    const float* __restrict__ W, __nv_bfloat16* __restrict__ th,
    __nv_bfloat16* __restrict__ tl)
{
    __shared__ float t[32][33];
    int k = blockIdx.y * 32 + threadIdx.y;
    int n = blockIdx.x * 32 + threadIdx.x;
    t[threadIdx.y][threadIdx.x] = W[k * 512 + n];
    __syncthreads();
    int nn = blockIdx.x * 32 + threadIdx.y;
    int kk = blockIdx.y * 32 + threadIdx.x;
    float v = t[threadIdx.x][threadIdx.y];
    __nv_bfloat16 h = __float2bfloat16(v);
    float lo = v - __bfloat162float(h);
    th[nn * 512 + kk] = h;
    tl[nn * 512 + kk] = __float2bfloat16(lo);
}

// ---------------- rmsnorm ---------------------------------------------------
__global__ __launch_bounds__(128) void rmsnorm_kernel(
    const float* __restrict__ x, const float* __restrict__ gamma,
    float* __restrict__ xn)
{
    const size_t row = blockIdx.x;
    const int tid = threadIdx.x;
    float4 v = ((const float4*)(x + row * DIM))[tid];
    float ss = v.x * v.x + v.y * v.y + v.z * v.z + v.w * v.w;
    #pragma unroll
    for (int o = 16; o; o >>= 1) ss += __shfl_xor_sync(0xffffffffu, ss, o);
    __shared__ float sred[4];
    if ((tid & 31) == 0) sred[tid >> 5] = ss;
    __syncthreads();
    float tot = sred[0] + sred[1] + sred[2] + sred[3];
    float n = fmaxf(sqrtf(tot), 1e-12f);
    float s = 22.62741699796952f / n;  // sqrt(512)
    float4 gv = ((const float4*)gamma)[tid];
    float4 o;
    o.x = v.x * s * (gv.x + 1.f);
    o.y = v.y * s * (gv.y + 1.f);
    o.z = v.z * s * (gv.z + 1.f);
    o.w = v.w * s * (gv.w + 1.f);
    ((float4*)(xn + row * DIM))[tid] = o;
}

// ---------------- HMMA split-bf16 GEMM --------------------------------------
// C[M,512] = act( A[M,512] @ W[512,512] [ + A2 @ W2 ] ), fp32 in/out.
// mma.sync m16n8k16 bf16, fp32 accum, 3-pass hi/lo split.
// CTA tile 128x128, 8 warps (4m x 2n), warp tile 32x64, BK=32, double buffer.
// smem rows padded to 80B -> conflict-free ldmatrix.
#define TILE_B 10240          // 128 rows * 80 B
#define BUF_B  (4 * TILE_B)   // Ah, Al, Bh, Bl
#define GSMH   (2 * BUF_B)    // 81920
__global__ __launch_bounds__(256, 2) void gemm_tc(
    const float* __restrict__ A,
    const __nv_bfloat16* __restrict__ WTh, const __nv_bfloat16* __restrict__ WTl,
    const float* __restrict__ A2,
    const __nv_bfloat16* __restrict__ W2h, const __nv_bfloat16* __restrict__ W2l,
    float* __restrict__ C, int act)
{
    extern __shared__ char smem[];
    const u32 sb = s2u(smem);
    const int tid = threadIdx.x;
    const int wid = tid >> 5;
    const int l = tid & 31;
    const int wm = wid >> 1, wn = wid & 1;
    const size_t m0 = (size_t)blockIdx.y * 128;
    const int n0 = blockIdx.x * 128;

    float acc[2][8][4];
    #pragma unroll
    for (int i = 0; i < 2; i++)
        #pragma unroll
        for (int j = 0; j < 8; j++)
            #pragma unroll
            for (int q = 0; q < 4; q++) acc[i][j][q] = 0.f;

    // ---- load thread mapping: row r, col half c0 ----
    const int r = tid >> 1;
    const int c0 = (tid & 1) * 16;       // element offset within BK=32
    const u32 rowb = (u32)r * 80 + (u32)c0 * 2;

    // ---- ldmatrix per-thread address components ----
    const u32 aRow = (u32)(l & 15);
    const u32 aK16 = (u32)((l >> 4) * 16);          // bytes
    const u32 bRow = (u32)((l >> 4) * 8 + (l & 7));
    const u32 bK16 = (u32)(((l >> 3) & 1) * 16);    // bytes

    const int nchunks = A2 ? 32 : 16;

    // prologue: chunk 0 -> buffer 0
    {
        const float* ab = A + (m0 + r) * 512 + c0;
        const __nv_bfloat16* bhp = WTh + (size_t)(n0 + r) * 512 + c0;
        const __nv_bfloat16* blp = WTl + (size_t)(n0 + r) * 512 + c0;
        #pragma unroll
        for (int i = 0; i < 2; i++) {   // two uint4 (8 elems each)
            float4 v0 = *(const float4*)(ab + i * 8);
            float4 v1 = *(const float4*)(ab + i * 8 + 4);
            uint4 uh, ul;
            cvt_hilo(v0, uh.x, uh.y, ul.x, ul.y);
            cvt_hilo(v1, uh.z, uh.w, ul.z, ul.w);
            *(uint4*)(smem + rowb + i * 16) = uh;
            *(uint4*)(smem + TILE_B + rowb + i * 16) = ul;
            *(uint4*)(smem + 2 * TILE_B + rowb + i * 16) = *(const uint4*)(bhp + i * 8);
            *(uint4*)(smem + 3 * TILE_B + rowb + i * 16) = *(const uint4*)(blp + i * 8);
        }
    }
    __syncthreads();

    for (int nc = 0; nc < nchunks; nc++) {
        const u32 buf = (u32)(nc & 1) * BUF_B;
        // ---- LDG next chunk into registers ----
        float4 av[4];
        uint4 bhv[2], blv[2];
        const bool has_next = (nc + 1 < nchunks);
        if (has_next) {
            const int nn = nc + 1;
            const int kc = (nn & 15) * 32;
            const float* Ap = (nn < 16) ? A : A2;
            const __nv_bfloat16* Bhp = (nn < 16) ? WTh : W2h;
            const __nv_bfloat16* Blp = (nn < 16) ? WTl : W2l;
            const float* ab = Ap + (m0 + r) * 512 + kc + c0;
            const __nv_bfloat16* bhp = Bhp + (size_t)(n0 + r) * 512 + kc + c0;
            const __nv_bfloat16* blp = Blp + (size_t)(n0 + r) * 512 + kc + c0;
            #pragma unroll
            for (int i = 0; i < 4; i++) av[i] = *(const float4*)(ab + i * 4);
            #pragma unroll
            for (int i = 0; i < 2; i++) {
                bhv[i] = *(const uint4*)(bhp + i * 8);
                blv[i] = *(const uint4*)(blp + i * 8);
            }
        }

        // ---- MMA on current buffer ----
        const u32 sA = sb + buf;
        const u32 sAl_ = sA + TILE_B;
        const u32 sB = sA + 2 * TILE_B;
        const u32 sBl_ = sA + 3 * TILE_B;
        #pragma unroll
        for (int ks = 0; ks < 2; ks++) {
            const u32 kb = (u32)ks * 32;  // bytes (16 elems)
            u32 ah[2][4], al[2][4];
            #pragma unroll
            for (int mt = 0; mt < 2; mt++) {
                u32 ra = (u32)(wm * 32 + mt * 16 + aRow) * 80 + kb + aK16;
                ldsm4(ah[mt][0], ah[mt][1], ah[mt][2], ah[mt][3], sA + ra);
                ldsm4(al[mt][0], al[mt][1], al[mt][2], al[mt][3], sAl_ + ra);
            }
            #pragma unroll
            for (int j = 0; j < 4; j++) {
                u32 rb = (u32)(wn * 64 + j * 16 + bRow) * 80 + kb + bK16;
                u32 bh[4], bl[4];
                ldsm4(bh[0], bh[1], bh[2], bh[3], sB + rb);
                ldsm4(bl[0], bl[1], bl[2], bl[3], sBl_ + rb);
                #pragma unroll
                for (int mt = 0; mt < 2; mt++) {
                    mma16816(acc[mt][2 * j],     ah[mt], &bh[0]);
                    mma16816(acc[mt][2 * j + 1], ah[mt], &bh[2]);
                    mma16816(acc[mt][2 * j],     ah[mt], &bl[0]);
                    mma16816(acc[mt][2 * j + 1], ah[mt], &bl[2]);
                    mma16816(acc[mt][2 * j],     al[mt], &bh[0]);
                    mma16816(acc[mt][2 * j + 1], al[mt], &bh[2]);
                }
            }
        }

        // ---- STS next chunk into other buffer ----
        if (has_next) {
            const u32 ob = (u32)((nc + 1) & 1) * BUF_B;
            #pragma unroll
            for (int i = 0; i < 2; i++) {
                uint4 uh, ul;
                cvt_hilo(av[2 * i],     uh.x, uh.y, ul.x, ul.y);
                cvt_hilo(av[2 * i + 1], uh.z, uh.w, ul.z, ul.w);
                *(uint4*)(smem + ob + rowb + i * 16) = uh;
                *(uint4*)(smem + ob + TILE_B + rowb + i * 16) = ul;
                *(uint4*)(smem + ob + 2 * TILE_B + rowb + i * 16) = bhv[i];
                *(uint4*)(smem + ob + 3 * TILE_B + rowb + i * 16) = blv[i];
            }
            __syncthreads();
        }
    }

    // ---- epilogue ----
    #pragma unroll
    for (int mt = 0; mt < 2; mt++) {
        size_t row0 = m0 + wm * 32 + mt * 16 + (l >> 2);
        #pragma unroll
        for (int nt = 0; nt < 8; nt++) {
            int col = n0 + wn * 64 + nt * 8 + (l & 3) * 2;
            float2 v0 = make_float2(acc[mt][nt][0], acc[mt][nt][1]);
            float2 v1 = make_float2(acc[mt][nt][2], acc[mt][nt][3]);
            if (act) {
                v0.x = tanhf(v0.x); v0.y = tanhf(v0.y);
                v1.x = tanhf(v1.x); v1.y = tanhf(v1.y);
            }
            *(float2*)(C + row0 * 512 + col) = v0;
            *(float2*)(C + (row0 + 8) * 512 + col) = v1;
        }
    }
}

// ---------------- LRU recurrence (unchanged) --------------------------------
__global__ void __cluster_dims__(8, 1, 1) __launch_bounds__(512, 1)
lru_scan(const float* __restrict__ nh, const float* __restrict__ ifg,
         const float* __restrict__ Whf, const float* __restrict__ bhf,
         float* __restrict__ hout)
{
    __shared__ __align__(16) float hbuf[2][2][DIM];   // [buffer][batch][j]
    __shared__ __align__(16) float stage[2][4][64];   // [buffer][nh0,if0,nh1,if1][jl]
    const u32 tid = threadIdx.x;
    const u32 jl = tid >> 3, s = tid & 7;
    u32 crank; asm("mov.u32 %0, %%cluster_ctarank;" : "=r"(crank));
    const u32 j = crank * 64 + jl;
    const u32 cl = blockIdx.x >> 3;

    u64 wp[32];
    #pragma unroll
    for (int ii = 0; ii < 16; ii++) {
        u32 i4 = (ii + s) & 15;
        u32 k = s * 64 + i4 * 4;
        float w0 = Whf[(size_t)(k + 0) * DIM + j];
        float w1 = Whf[(size_t)(k + 1) * DIM + j];
        float w2 = Whf[(size_t)(k + 2) * DIM + j];
        float w3 = Whf[(size_t)(k + 3) * DIM + j];
        wp[2 * ii] = pk2(w0, w1);
        wp[2 * ii + 1] = pk2(w2, w3);
    }
    const float bias = bhf[j];

    hbuf[0][0][tid] = 0.f;
    hbuf[0][1][tid] = 0.f;

    u32 a00 = s2u(&hbuf[0][0][j]), a01 = s2u(&hbuf[0][1][j]);
    u32 a10 = s2u(&hbuf[1][0][j]), a11 = s2u(&hbuf[1][1][j]);
    u32 r00, r01, r10, r11;
    asm("mapa.shared::cluster.u32 %0, %1, %2;" : "=r"(r00) : "r"(a00), "r"(s));
    asm("mapa.shared::cluster.u32 %0, %1, %2;" : "=r"(r01) : "r"(a01), "r"(s));
    asm("mapa.shared::cluster.u32 %0, %1, %2;" : "=r"(r10) : "r"(a10), "r"(s));
    asm("mapa.shared::cluster.u32 %0, %1, %2;" : "=r"(r11) : "r"(a11), "r"(s));

    const u32 sel = tid >> 4;
    const u32 f4 = tid & 15;
    const float* lp = nullptr;
    if (tid < 64) {
        const float* arr = (sel & 1) ? ifg : nh;
        u32 b = sel >> 1;
        lp = arr + ((size_t)(cl * 2 + b) * TLEN) * DIM + crank * 64 + f4 * 4;
        float4 v = *(const float4*)lp;          // t = 0
        *(float4*)&stage[0][sel][f4 * 4] = v;
    }

    const size_t obase0 = ((size_t)(cl * 2 + 0) * TLEN) * DIM + j;
    const size_t obase1 = ((size_t)(cl * 2 + 1) * TLEN) * DIM + j;

    __syncthreads();
    CLUSTER_SYNC();

    float h0 = 0.f, h1 = 0.f;
    int p = 0;
    for (int t = 0; t < TLEN; t++) {
        const int sb2 = t & 1;
        float4 pv;
        const bool do_pref = (tid < 64) && (t + 1 < TLEN);
        if (do_pref) pv = *(const float4*)(lp + (size_t)(t + 1) * DIM);

        const ulonglong2* hq0 = (const ulonglong2*)hbuf[p][0];
        const ulonglong2* hq1 = (const ulonglong2*)hbuf[p][1];
        u64 acc0a = 0ull, acc0b = 0ull, acc1a = 0ull, acc1b = 0ull;
        #pragma unroll
        for (int ii = 0; ii < 16; ii++) {
            u32 idx = s * 16 + ((ii + s) & 15);
            ulonglong2 hv0 = hq0[idx];
            ulonglong2 hv1 = hq1[idx];
            FMA2(acc0a, wp[2 * ii], hv0.x);
            FMA2(acc0b, wp[2 * ii + 1], hv0.y);
            FMA2(acc1a, wp[2 * ii], hv1.x);
            FMA2(acc1b, wp[2 * ii + 1], hv1.y);
        }
        float2 u0 = up2(acc0a), u0b = up2(acc0b);
        float2 u1 = up2(acc1a), u1b = up2(acc1b);
        float d0 = (u0.x + u0.y) + (u0b.x + u0b.y);
        float d1 = (u1.x + u1.y) + (u1b.x + u1b.y);
        d0 += __shfl_xor_sync(0xffffffffu, d0, 1);
        d0 += __shfl_xor_sync(0xffffffffu, d0, 2);
        d0 += __shfl_xor_sync(0xffffffffu, d0, 4);
        d1 += __shfl_xor_sync(0xffffffffu, d1, 1);
        d1 += __shfl_xor_sync(0xffffffffu, d1, 2);
        d1 += __shfl_xor_sync(0xffffffffu, d1, 4);

        const float nv0 = stage[sb2][0][jl], iv0 = stage[sb2][1][jl];
        const float nv1 = stage[sb2][2][jl], iv1 = stage[sb2][3][jl];

        float g0 = 1.f / (1.f + expf(-(d0 + bias + iv0)));
        float g1 = 1.f / (1.f + expf(-(d1 + bias + iv1)));
        float hn0 = fmaf(g0, nv0 - h0, h0);
        float hn1 = fmaf(g1, nv1 - h1, h1);
        h0 = hn0; h1 = hn1;

        u32 d0a = p ? r00 : r10;  // write buffer p^1
        u32 d1a = p ? r01 : r11;
        asm volatile("st.shared::cluster.f32 [%0], %1;" :: "r"(d0a), "f"(hn0) : "memory");
        asm volatile("st.shared::cluster.f32 [%0], %1;" :: "r"(d1a), "f"(hn1) : "memory");
        if (s == 0) {
            hout[obase0 + (size_t)t * DIM] = hn0;
            hout[obase1 + (size_t)t * DIM] = hn1;
        }
        if (do_pref) *(float4*)&stage[sb2 ^ 1][sel][f4 * 4] = pv;
        CLUSTER_SYNC();
        p ^= 1;
    }
}

// ---------------- final fuse: out = x + xn + sig(gl + b) * (gnh - xn) -------
__global__ __launch_bounds__(256) void final_kernel(
    const float* __restrict__ x, const float* __restrict__ xn,
    const float* __restrict__ gnh, const float* __restrict__ gl,
    const float* __restrict__ bhf, float* __restrict__ out)
{
    size_t i = (size_t)blockIdx.x * blockDim.x + threadIdx.x;  // float4 idx
    if (i >= (size_t)MROWS * DIM / 4) return;
    float4 xv = ((const float4*)x)[i];
    float4 nx = ((const float4*)xn)[i];
    float4 nv = ((const float4*)gnh)[i];
    float4 lv = ((const float4*)gl)[i];
    float4 bv = ((const float4*)bhf)[i & 127];
    float4 o;
    o.x = xv.x + nx.x + (nv.x - nx.x) / (1.f + expf(-(lv.x + bv.x)));
    o.y = xv.y + nx.y + (nv.y - nx.y) / (1.f + expf(-(lv.y + bv.y)));
    o.z = xv.z + nx.z + (nv.z - nx.z) / (1.f + expf(-(lv.z + bv.z)));
    o.w = xv.w + nx.w + (nv.w - nx.w) / (1.f + expf(-(lv.w + bv.w)));
    ((float4*)out)[i] = o;
}

// ---------------- host -------------------------------------------------------
extern "C" void kernel_launch(void* const* d_in, const int* in_sizes, int n_in,
                              void* d_out, int out_size)
{
    (void)in_sizes; (void)n_in; (void)out_size;
    const float* x      = (const float*)d_in[0];
    const float* gamma  = (const float*)d_in[1];
    const float* g_Wn   = (const float*)d_in[2];
    const float* g_Wif  = (const float*)d_in[3];
    const float* g_Whf  = (const float*)d_in[4];
    const float* g_bhf  = (const float*)d_in[5];
    const float* l0_Wn  = (const float*)d_in[6];
    const float* l0_Wif = (const float*)d_in[7];
    const float* l0_Whf = (const float*)d_in[8];
    const float* l0_bhf = (const float*)d_in[9];
    const float* l1_Wn  = (const float*)d_in[10];
    const float* l1_Wif = (const float*)d_in[11];
    const float* l1_Whf = (const float*)d_in[12];
    const float* l1_bhf = (const float*)d_in[13];
    float* out = (float*)d_out;

    float *S0, *S1, *S2, *S3;
    __nv_bfloat16 *Wh, *Wl;
    cudaGetSymbolAddress((void**)&S0, g_S0);
    cudaGetSymbolAddress((void**)&S1, g_S1);
    cudaGetSymbolAddress((void**)&S2, g_S2);
    cudaGetSymbolAddress((void**)&S3, g_S3);
    cudaGetSymbolAddress((void**)&Wh, g_WTh);
    cudaGetSymbolAddress((void**)&Wl, g_WTl);

    cudaFuncSetAttribute(gemm_tc, cudaFuncAttributeMaxDynamicSharedMemorySize, GSMH);

    // weight prep: idx 0:l0_Wn 1:l0_Wif 2:l1_Wn 3:l1_Wif 4:g_Wn 5:g_Whf 6:g_Wif
    const float* Ws[7] = {l0_Wn, l0_Wif, l1_Wn, l1_Wif, g_Wn, g_Whf, g_Wif};
    dim3 pg(16, 16), pb(32, 32);
    for (int i = 0; i < 7; i++)
        prep_w<<<pg, pb>>>(Ws[i], Wh + (size_t)i * 512 * 512, Wl + (size_t)i * 512 * 512);

    rmsnorm_kernel<<<MROWS, 128>>>(x, gamma, S0);

    dim3 gg(4, 512);  // N tiles x M tiles
    #define WH(i) (Wh + (size_t)(i) * 512 * 512)
    #define WL_(i) (Wl + (size_t)(i) * 512 * 512)
    const __nv_bfloat16* nb = nullptr;

    gemm_tc<<<gg, 256, GSMH>>>(S0, WH(0), WL_(0), nullptr, nb, nb, S1, 1);    // nh0
    gemm_tc<<<gg, 256, GSMH>>>(S0, WH(1), WL_(1), nullptr, nb, nb, S2, 0);    // if0
    lru_scan<<<128, 512>>>(S1, S2, l0_Whf, l0_bhf, S3);                        // h0

    gemm_tc<<<gg, 256, GSMH>>>(S3, WH(2), WL_(2), nullptr, nb, nb, S1, 1);    // nh1
    gemm_tc<<<gg, 256, GSMH>>>(S3, WH(3), WL_(3), nullptr, nb, nb, S2, 0);    // if1
    lru_scan<<<128, 512>>>(S1, S2, l1_Whf, l1_bhf, S3);                        // h1

    gemm_tc<<<gg, 256, GSMH>>>(S3, WH(4), WL_(4), nullptr, nb, nb, S1, 1);    // gnh
    gemm_tc<<<gg, 256, GSMH>>>(S0, WH(5), WL_(5), S3, WH(6), WL_(6), S2, 0);  // gl (K=1024 fused)

    final_kernel<<<32768, 256>>>(x, S0, S1, S2, g_bhf, out);
}

// round 17
// speedup vs baseline: 1.7444x; 1.0175x over previous
#include <cuda_runtime.h>
#include <cuda_bf16.h>
#include <cstdint>
#include <math.h>

#define DIM   512
#define BATCH 32
#define TLEN  2048
#define MROWS (BATCH * TLEN)

typedef unsigned long long u64;
typedef unsigned int u32;

// ---------------- scratch (device globals; no allocation allowed) ----------
__device__ float g_S0[(size_t)MROWS * DIM];  // xn
__device__ float g_S1[(size_t)MROWS * DIM];  // nh / gnh
__device__ float g_S2[(size_t)MROWS * DIM];  // ifg / gate logits
__device__ float g_S3[(size_t)MROWS * DIM];  // h (layer outputs)
// transposed + hi/lo split weights (bf16), [widx][n*512 + k]
__device__ __nv_bfloat16 g_WTh[7][512 * 512];
__device__ __nv_bfloat16 g_WTl[7][512 * 512];

// ---------------- helpers ---------------------------------------------------
__device__ __forceinline__ u64 pk2(float x, float y) {
    u64 r; asm("mov.b64 %0, {%1,%2};" : "=l"(r) : "f"(x), "f"(y)); return r;
}
__device__ __forceinline__ float2 up2(u64 v) {
    float2 r; asm("mov.b64 {%0,%1}, %2;" : "=f"(r.x), "=f"(r.y) : "l"(v)); return r;
}
#define FMA2(d, a, b) asm("fma.rn.f32x2 %0, %1, %2, %0;" : "+l"(d) : "l"(a), "l"(b))

__device__ __forceinline__ u32 s2u(const void* p) {
    u32 a;
    asm("{ .reg .u64 t; cvta.to.shared.u64 t, %1; cvt.u32.u64 %0, t; }" : "=r"(a) : "l"(p));
    return a;
}
#define CLUSTER_SYNC() do { \
    asm volatile("barrier.cluster.arrive.aligned;" ::: "memory"); \
    asm volatile("barrier.cluster.wait.aligned;" ::: "memory"); \
} while (0)

#define CPASYNC16(dst, src) \
    asm volatile("cp.async.ca.shared.global [%0], [%1], 16;" :: "r"(dst), "l"(src))
#define CPCOMMIT() asm volatile("cp.async.commit_group;" ::: "memory")
#define CPWAIT0()  asm volatile("cp.async.wait_group 0;" ::: "memory")

__device__ __forceinline__ void ldsm4(u32& r0, u32& r1, u32& r2, u32& r3, u32 addr) {
    asm volatile("ldmatrix.sync.aligned.m8n8.x4.shared.b16 {%0,%1,%2,%3}, [%4];"
                 : "=r"(r0), "=r"(r1), "=r"(r2), "=r"(r3) : "r"(addr));
}
__device__ __forceinline__ void mma16816(float* c, const u32* a, const u32* b) {
    asm volatile(
        "mma.sync.aligned.m16n8k16.row.col.f32.bf16.bf16.f32 "
        "{%0,%1,%2,%3}, {%4,%5,%6,%7}, {%8,%9}, {%0,%1,%2,%3};"
        : "+f"(c[0]), "+f"(c[1]), "+f"(c[2]), "+f"(c[3])
        : "r"(a[0]), "r"(a[1]), "r"(a[2]), "r"(a[3]), "r"(b[0]), "r"(b[1]));
}

// split one float4 into hi/lo bf16 pairs (2x u32 each)
__device__ __forceinline__ void cvt_hilo(float4 v, u32& h01, u32& h23, u32& l01, u32& l23) {
    __nv_bfloat16 hx = __float2bfloat16(v.x), hy = __float2bfloat16(v.y);
    __nv_bfloat16 hz = __float2bfloat16(v.z), hw = __float2bfloat16(v.w);
    __nv_bfloat162 H0 = __halves2bfloat162(hx, hy), H1 = __halves2bfloat162(hz, hw);
    float lx = v.x - __bfloat162float(hx), ly = v.y - __bfloat162float(hy);
    float lz = v.z - __bfloat162float(hz), lw = v.w - __bfloat162float(hw);
    __nv_bfloat162 L0 = __floats2bfloat162_rn(lx, ly), L1 = __floats2bfloat162_rn(lz, lw);
    h01 = *(u32*)&H0; h23 = *(u32*)&H1;
    l01 = *(u32*)&L0; l23 = *(u32*)&L1;
}

// ---------------- weight prep (ONE launch, z = weight index) -----------------
__global__ __launch_bounds__(1024) void prep_w_all(
    const float* W0, const float* W1, const float* W2, const float* W3,
    const float* W4, const float* W5, const float* W6,
    __nv_bfloat16* __restrict__ thb, __nv_bfloat16* __restrict__ tlb)
{
    const float* Ws[7] = {W0, W1, W2, W3, W4, W5, W6};
    const float* W = Ws[blockIdx.z];
    __nv_bfloat16* th = thb + (size_t)blockIdx.z * 512 * 512;
    __nv_bfloat16* tl = tlb + (size_t)blockIdx.z * 512 * 512;
    __shared__ float t[32][33];
    int k = blockIdx.y * 32 + threadIdx.y;
    int n = blockIdx.x * 32 + threadIdx.x;
    t[threadIdx.y][threadIdx.x] = W[k * 512 + n];
    __syncthreads();
    int nn = blockIdx.x * 32 + threadIdx.y;
    int kk = blockIdx.y * 32 + threadIdx.x;
    float v = t[threadIdx.x][threadIdx.y];
    __nv_bfloat16 h = __float2bfloat16(v);
    float lo = v - __bfloat162float(h);
    th[nn * 512 + kk] = h;
    tl[nn * 512 + kk] = __float2bfloat16(lo);
}

// ---------------- rmsnorm ---------------------------------------------------
__global__ __launch_bounds__(128) void rmsnorm_kernel(
    const float* __restrict__ x, const float* __restrict__ gamma,
    float* __restrict__ xn)
{
    const size_t row = blockIdx.x;
    const int tid = threadIdx.x;
    float4 v = ((const float4*)(x + row * DIM))[tid];
    float ss = v.x * v.x + v.y * v.y + v.z * v.z + v.w * v.w;
    #pragma unroll
    for (int o = 16; o; o >>= 1) ss += __shfl_xor_sync(0xffffffffu, ss, o);
    __shared__ float sred[4];
    if ((tid & 31) == 0) sred[tid >> 5] = ss;
    __syncthreads();
    float tot = sred[0] + sred[1] + sred[2] + sred[3];
    float n = fmaxf(sqrtf(tot), 1e-12f);
    float s = 22.62741699796952f / n;  // sqrt(512)
    float4 gv = ((const float4*)gamma)[tid];
    float4 o;
    o.x = v.x * s * (gv.x + 1.f);
    o.y = v.y * s * (gv.y + 1.f);
    o.z = v.z * s * (gv.z + 1.f);
    o.w = v.w * s * (gv.w + 1.f);
    ((float4*)(xn + row * DIM))[tid] = o;
}

// ---------------- HMMA split-bf16 GEMM --------------------------------------
// C[M,512] = act( A[M,512] @ W[512,512] [ + A2 @ W2 ] ), fp32 in/out.
// mma.sync m16n8k16 bf16, fp32 accum, 3-pass hi/lo split.
// CTA tile 128x128, 8 warps (4m x 2n), warp tile 32x64, BK=32, double buffer.
// B tiles move via cp.async (no register staging); A converted in-regs.
// smem rows padded to 80B -> conflict-free ldmatrix; 80 = 5*16 keeps 16B align.
#define TILE_B 10240          // 128 rows * 80 B
#define BUF_B  (4 * TILE_B)   // Ah, Al, Bh, Bl
#define GSMH   (2 * BUF_B)    // 81920
__global__ __launch_bounds__(256, 2) void gemm_tc(
    const float* __restrict__ A,
    const __nv_bfloat16* __restrict__ WTh, const __nv_bfloat16* __restrict__ WTl,
    const float* __restrict__ A2,
    const __nv_bfloat16* __restrict__ W2h, const __nv_bfloat16* __restrict__ W2l,
    float* __restrict__ C, int act)
{
    extern __shared__ char smem[];
    const u32 sb = s2u(smem);
    const int tid = threadIdx.x;
    const int wid = tid >> 5;
    const int l = tid & 31;
    const int wm = wid >> 1, wn = wid & 1;
    const size_t m0 = (size_t)blockIdx.y * 128;
    const int n0 = blockIdx.x * 128;

    float acc[2][8][4];
    #pragma unroll
    for (int i = 0; i < 2; i++)
        #pragma unroll
        for (int j = 0; j < 8; j++)
            #pragma unroll
            for (int q = 0; q < 4; q++) acc[i][j][q] = 0.f;

    // ---- load thread mapping: row r, col half c0 ----
    const int r = tid >> 1;
    const int c0 = (tid & 1) * 16;       // element offset within BK=32
    const u32 rowb = (u32)r * 80 + (u32)c0 * 2;   // always 16B aligned (80=5*16)

    // ---- ldmatrix per-thread address components ----
    const u32 aRow = (u32)(l & 15);
    const u32 aK16 = (u32)((l >> 4) * 16);          // bytes
    const u32 bRow = (u32)((l >> 4) * 8 + (l & 7));
    const u32 bK16 = (u32)(((l >> 3) & 1) * 16);    // bytes

    const int nchunks = A2 ? 32 : 16;

    // ---- helpers as lambdas ----
    auto issueB = [&](int nn, u32 ob) {
        const int kc = (nn & 15) * 32;
        const __nv_bfloat16* Bhp = (nn < 16) ? WTh : W2h;
        const __nv_bfloat16* Blp = (nn < 16) ? WTl : W2l;
        const __nv_bfloat16* bhp = Bhp + (size_t)(n0 + r) * 512 + kc + c0;
        const __nv_bfloat16* blp = Blp + (size_t)(n0 + r) * 512 + kc + c0;
        #pragma unroll
        for (int i = 0; i < 2; i++) {
            CPASYNC16(sb + ob + 2 * TILE_B + rowb + i * 16, bhp + i * 8);
            CPASYNC16(sb + ob + 3 * TILE_B + rowb + i * 16, blp + i * 8);
        }
        CPCOMMIT();
    };
    auto loadA = [&](int nn, float4* av) {
        const int kc = (nn & 15) * 32;
        const float* Ap = (nn < 16) ? A : A2;
        const float* ab = Ap + (m0 + r) * 512 + kc + c0;
        #pragma unroll
        for (int i = 0; i < 4; i++) av[i] = *(const float4*)(ab + i * 4);
    };
    auto storeA = [&](const float4* av, u32 ob) {
        #pragma unroll
        for (int i = 0; i < 2; i++) {
            uint4 uh, ul;
            cvt_hilo(av[2 * i],     uh.x, uh.y, ul.x, ul.y);
            cvt_hilo(av[2 * i + 1], uh.z, uh.w, ul.z, ul.w);
            *(uint4*)(smem + ob + rowb + i * 16) = uh;
            *(uint4*)(smem + ob + TILE_B + rowb + i * 16) = ul;
        }
    };

    // prologue: chunk 0 -> buffer 0
    {
        issueB(0, 0);
        float4 av[4];
        loadA(0, av);
        storeA(av, 0);
        CPWAIT0();
    }
    __syncthreads();

    for (int nc = 0; nc < nchunks; nc++) {
        const u32 buf = (u32)(nc & 1) * BUF_B;
        const u32 ob = (u32)((nc + 1) & 1) * BUF_B;
        const bool has_next = (nc + 1 < nchunks);

        float4 av[4];
        if (has_next) {
            issueB(nc + 1, ob);     // cp.async straight into back buffer
            loadA(nc + 1, av);      // A staged in regs (needs conversion)
        }

        // ---- MMA on current buffer ----
        const u32 sA = sb + buf;
        const u32 sAl_ = sA + TILE_B;
        const u32 sB = sA + 2 * TILE_B;
        const u32 sBl_ = sA + 3 * TILE_B;
        #pragma unroll
        for (int ks = 0; ks < 2; ks++) {
            const u32 kb = (u32)ks * 32;  // bytes (16 elems)
            u32 ah[2][4], al[2][4];
            #pragma unroll
            for (int mt = 0; mt < 2; mt++) {
                u32 ra = (u32)(wm * 32 + mt * 16 + aRow) * 80 + kb + aK16;
                ldsm4(ah[mt][0], ah[mt][1], ah[mt][2], ah[mt][3], sA + ra);
                ldsm4(al[mt][0], al[mt][1], al[mt][2], al[mt][3], sAl_ + ra);
            }
            #pragma unroll
            for (int j = 0; j < 4; j++) {
                u32 rb = (u32)(wn * 64 + j * 16 + bRow) * 80 + kb + bK16;
                u32 bh[4], bl[4];
                ldsm4(bh[0], bh[1], bh[2], bh[3], sB + rb);
                ldsm4(bl[0], bl[1], bl[2], bl[3], sBl_ + rb);
                #pragma unroll
                for (int mt = 0; mt < 2; mt++) {
                    mma16816(acc[mt][2 * j],     ah[mt], &bh[0]);
                    mma16816(acc[mt][2 * j + 1], ah[mt], &bh[2]);
                    mma16816(acc[mt][2 * j],     ah[mt], &bl[0]);
                    mma16816(acc[mt][2 * j + 1], ah[mt], &bl[2]);
                    mma16816(acc[mt][2 * j],     al[mt], &bh[0]);
                    mma16816(acc[mt][2 * j + 1], al[mt], &bh[2]);
                }
            }
        }

        if (has_next) {
            storeA(av, ob);
            CPWAIT0();
            __syncthreads();
        }
    }

    // ---- epilogue ----
    #pragma unroll
    for (int mt = 0; mt < 2; mt++) {
        size_t row0 = m0 + wm * 32 + mt * 16 + (l >> 2);
        #pragma unroll
        for (int nt = 0; nt < 8; nt++) {
            int col = n0 + wn * 64 + nt * 8 + (l & 3) * 2;
            float2 v0 = make_float2(acc[mt][nt][0], acc[mt][nt][1]);
            float2 v1 = make_float2(acc[mt][nt][2], acc[mt][nt][3]);
            if (act) {
                v0.x = tanhf(v0.x); v0.y = tanhf(v0.y);
                v1.x = tanhf(v1.x); v1.y = tanhf(v1.y);
            }
            *(float2*)(C + row0 * 512 + col) = v0;
            *(float2*)(C + (row0 + 8) * 512 + col) = v1;
        }
    }
}

// ---------------- LRU recurrence (unchanged) --------------------------------
__global__ void __cluster_dims__(8, 1, 1) __launch_bounds__(512, 1)
lru_scan(const float* __restrict__ nh, const float* __restrict__ ifg,
         const float* __restrict__ Whf, const float* __restrict__ bhf,
         float* __restrict__ hout)
{
    __shared__ __align__(16) float hbuf[2][2][DIM];   // [buffer][batch][j]
    __shared__ __align__(16) float stage[2][4][64];   // [buffer][nh0,if0,nh1,if1][jl]
    const u32 tid = threadIdx.x;
    const u32 jl = tid >> 3, s = tid & 7;
    u32 crank; asm("mov.u32 %0, %%cluster_ctarank;" : "=r"(crank));
    const u32 j = crank * 64 + jl;
    const u32 cl = blockIdx.x >> 3;

    u64 wp[32];
    #pragma unroll
    for (int ii = 0; ii < 16; ii++) {
        u32 i4 = (ii + s) & 15;
        u32 k = s * 64 + i4 * 4;
        float w0 = Whf[(size_t)(k + 0) * DIM + j];
        float w1 = Whf[(size_t)(k + 1) * DIM + j];
        float w2 = Whf[(size_t)(k + 2) * DIM + j];
        float w3 = Whf[(size_t)(k + 3) * DIM + j];
        wp[2 * ii] = pk2(w0, w1);
        wp[2 * ii + 1] = pk2(w2, w3);
    }
    const float bias = bhf[j];

    hbuf[0][0][tid] = 0.f;
    hbuf[0][1][tid] = 0.f;

    u32 a00 = s2u(&hbuf[0][0][j]), a01 = s2u(&hbuf[0][1][j]);
    u32 a10 = s2u(&hbuf[1][0][j]), a11 = s2u(&hbuf[1][1][j]);
    u32 r00, r01, r10, r11;
    asm("mapa.shared::cluster.u32 %0, %1, %2;" : "=r"(r00) : "r"(a00), "r"(s));
    asm("mapa.shared::cluster.u32 %0, %1, %2;" : "=r"(r01) : "r"(a01), "r"(s));
    asm("mapa.shared::cluster.u32 %0, %1, %2;" : "=r"(r10) : "r"(a10), "r"(s));
    asm("mapa.shared::cluster.u32 %0, %1, %2;" : "=r"(r11) : "r"(a11), "r"(s));

    const u32 sel = tid >> 4;
    const u32 f4 = tid & 15;
    const float* lp = nullptr;
    if (tid < 64) {
        const float* arr = (sel & 1) ? ifg : nh;
        u32 b = sel >> 1;
        lp = arr + ((size_t)(cl * 2 + b) * TLEN) * DIM + crank * 64 + f4 * 4;
        float4 v = *(const float4*)lp;          // t = 0
        *(float4*)&stage[0][sel][f4 * 4] = v;
    }

    const size_t obase0 = ((size_t)(cl * 2 + 0) * TLEN) * DIM + j;
    const size_t obase1 = ((size_t)(cl * 2 + 1) * TLEN) * DIM + j;

    __syncthreads();
    CLUSTER_SYNC();

    float h0 = 0.f, h1 = 0.f;
    int p = 0;
    for (int t = 0; t < TLEN; t++) {
        const int sb2 = t & 1;
        float4 pv;
        const bool do_pref = (tid < 64) && (t + 1 < TLEN);
        if (do_pref) pv = *(const float4*)(lp + (size_t)(t + 1) * DIM);

        const ulonglong2* hq0 = (const ulonglong2*)hbuf[p][0];
        const ulonglong2* hq1 = (const ulonglong2*)hbuf[p][1];
        u64 acc0a = 0ull, acc0b = 0ull, acc1a = 0ull, acc1b = 0ull;
        #pragma unroll
        for (int ii = 0; ii < 16; ii++) {
            u32 idx = s * 16 + ((ii + s) & 15);
            ulonglong2 hv0 = hq0[idx];
            ulonglong2 hv1 = hq1[idx];
            FMA2(acc0a, wp[2 * ii], hv0.x);
            FMA2(acc0b, wp[2 * ii + 1], hv0.y);
            FMA2(acc1a, wp[2 * ii], hv1.x);
            FMA2(acc1b, wp[2 * ii + 1], hv1.y);
        }
        float2 u0 = up2(acc0a), u0b = up2(acc0b);
        float2 u1 = up2(acc1a), u1b = up2(acc1b);
        float d0 = (u0.x + u0.y) + (u0b.x + u0b.y);
        float d1 = (u1.x + u1.y) + (u1b.x + u1b.y);
        d0 += __shfl_xor_sync(0xffffffffu, d0, 1);
        d0 += __shfl_xor_sync(0xffffffffu, d0, 2);
        d0 += __shfl_xor_sync(0xffffffffu, d0, 4);
        d1 += __shfl_xor_sync(0xffffffffu, d1, 1);
        d1 += __shfl_xor_sync(0xffffffffu, d1, 2);
        d1 += __shfl_xor_sync(0xffffffffu, d1, 4);

        const float nv0 = stage[sb2][0][jl], iv0 = stage[sb2][1][jl];
        const float nv1 = stage[sb2][2][jl], iv1 = stage[sb2][3][jl];

        float g0 = 1.f / (1.f + expf(-(d0 + bias + iv0)));
        float g1 = 1.f / (1.f + expf(-(d1 + bias + iv1)));
        float hn0 = fmaf(g0, nv0 - h0, h0);
        float hn1 = fmaf(g1, nv1 - h1, h1);
        h0 = hn0; h1 = hn1;

        u32 d0a = p ? r00 : r10;  // write buffer p^1
        u32 d1a = p ? r01 : r11;
        asm volatile("st.shared::cluster.f32 [%0], %1;" :: "r"(d0a), "f"(hn0) : "memory");
        asm volatile("st.shared::cluster.f32 [%0], %1;" :: "r"(d1a), "f"(hn1) : "memory");
        if (s == 0) {
            hout[obase0 + (size_t)t * DIM] = hn0;
            hout[obase1 + (size_t)t * DIM] = hn1;
        }
        if (do_pref) *(float4*)&stage[sb2 ^ 1][sel][f4 * 4] = pv;
        CLUSTER_SYNC();
        p ^= 1;
    }
}

// ---------------- final fuse: out = x + xn + sig(gl + b) * (gnh - xn) -------
__global__ __launch_bounds__(256) void final_kernel(
    const float* __restrict__ x, const float* __restrict__ xn,
    const float* __restrict__ gnh, const float* __restrict__ gl,
    const float* __restrict__ bhf, float* __restrict__ out)
{
    size_t i = (size_t)blockIdx.x * blockDim.x + threadIdx.x;  // float4 idx
    if (i >= (size_t)MROWS * DIM / 4) return;
    float4 xv = ((const float4*)x)[i];
    float4 nx = ((const float4*)xn)[i];
    float4 nv = ((const float4*)gnh)[i];
    float4 lv = ((const float4*)gl)[i];
    float4 bv = ((const float4*)bhf)[i & 127];
    float4 o;
    o.x = xv.x + nx.x + (nv.x - nx.x) / (1.f + expf(-(lv.x + bv.x)));
    o.y = xv.y + nx.y + (nv.y - nx.y) / (1.f + expf(-(lv.y + bv.y)));
    o.z = xv.z + nx.z + (nv.z - nx.z) / (1.f + expf(-(lv.z + bv.z)));
    o.w = xv.w + nx.w + (nv.w - nx.w) / (1.f + expf(-(lv.w + bv.w)));
    ((float4*)out)[i] = o;
}

// ---------------- host -------------------------------------------------------
extern "C" void kernel_launch(void* const* d_in, const int* in_sizes, int n_in,
                              void* d_out, int out_size)
{
    (void)in_sizes; (void)n_in; (void)out_size;
    const float* x      = (const float*)d_in[0];
    const float* gamma  = (const float*)d_in[1];
    const float* g_Wn   = (const float*)d_in[2];
    const float* g_Wif  = (const float*)d_in[3];
    const float* g_Whf  = (const float*)d_in[4];
    const float* g_bhf  = (const float*)d_in[5];
    const float* l0_Wn  = (const float*)d_in[6];
    const float* l0_Wif = (const float*)d_in[7];
    const float* l0_Whf = (const float*)d_in[8];
    const float* l0_bhf = (const float*)d_in[9];
    const float* l1_Wn  = (const float*)d_in[10];
    const float* l1_Wif = (const float*)d_in[11];
    const float* l1_Whf = (const float*)d_in[12];
    const float* l1_bhf = (const float*)d_in[13];
    float* out = (float*)d_out;

    float *S0, *S1, *S2, *S3;
    __nv_bfloat16 *Wh, *Wl;
    cudaGetSymbolAddress((void**)&S0, g_S0);
    cudaGetSymbolAddress((void**)&S1, g_S1);
    cudaGetSymbolAddress((void**)&S2, g_S2);
    cudaGetSymbolAddress((void**)&S3, g_S3);
    cudaGetSymbolAddress((void**)&Wh, g_WTh);
    cudaGetSymbolAddress((void**)&Wl, g_WTl);

    cudaFuncSetAttribute(gemm_tc, cudaFuncAttributeMaxDynamicSharedMemorySize, GSMH);

    // weight prep (1 launch): idx 0:l0_Wn 1:l0_Wif 2:l1_Wn 3:l1_Wif 4:g_Wn 5:g_Whf 6:g_Wif
    dim3 pg(16, 16, 7), pb(32, 32);
    prep_w_all<<<pg, pb>>>(l0_Wn, l0_Wif, l1_Wn, l1_Wif, g_Wn, g_Whf, g_Wif, Wh, Wl);

    rmsnorm_kernel<<<MROWS, 128>>>(x, gamma, S0);

    dim3 gg(4, 512);  // N tiles x M tiles
    #define WH(i) (Wh + (size_t)(i) * 512 * 512)
    #define WL_(i) (Wl + (size_t)(i) * 512 * 512)
    const __nv_bfloat16* nb = nullptr;

    gemm_tc<<<gg, 256, GSMH>>>(S0, WH(0), WL_(0), nullptr, nb, nb, S1, 1);    // nh0   (launch 3)
    gemm_tc<<<gg, 256, GSMH>>>(S0, WH(1), WL_(1), nullptr, nb, nb, S2, 0);    // if0   (launch 4)
    lru_scan<<<128, 512>>>(S1, S2, l0_Whf, l0_bhf, S3);                        // h0    (launch 5)

    gemm_tc<<<gg, 256, GSMH>>>(S3, WH(2), WL_(2), nullptr, nb, nb, S1, 1);    // nh1   (launch 6 — ncu target)
    gemm_tc<<<gg, 256, GSMH>>>(S3, WH(3), WL_(3), nullptr, nb, nb, S2, 0);    // if1
    lru_scan<<<128, 512>>>(S1, S2, l1_Whf, l1_bhf, S3);                        // h1

    gemm_tc<<<gg, 256, GSMH>>>(S3, WH(4), WL_(4), nullptr, nb, nb, S1, 1);    // gnh
    gemm_tc<<<gg, 256, GSMH>>>(S0, WH(5), WL_(5), S3, WH(6), WL_(6), S2, 0);  // gl (K=1024 fused)

    final_kernel<<<32768, 256>>>(x, S0, S1, S2, g_bhf, out);
}